// round 12
// baseline (speedup 1.0000x reference)
#include <cuda_runtime.h>
#include <cuda_bf16.h>
#include <cstdint>

// Problem constants
#define B_SZ   1024
#define T_SZ   4
#define D_IN   768
#define D_SAE  16384
#define K_TOP  64
#define K_DIM  3072
#define TD     3072

// ---------------------------------------------------------------------------
// Device scratch (no allocation allowed)
// ---------------------------------------------------------------------------
__device__ __nv_bfloat16 g_xhi[B_SZ * K_DIM];
__device__ __nv_bfloat16 g_xlo[B_SZ * K_DIM];
__device__ __nv_bfloat16 g_whi[(size_t)D_SAE * K_DIM];   // W^T hi, (N, K) row-major
__device__ __nv_bfloat16 g_wlo[(size_t)D_SAE * K_DIM];   // W^T lo
__device__ int   g_idx[B_SZ * K_TOP];
__device__ float g_val[B_SZ * K_TOP];

// ---------------------------------------------------------------------------
// PTX helpers (base sm_80+ features only: cp.async, ldmatrix, mma.sync)
// ---------------------------------------------------------------------------
static __device__ __forceinline__ uint32_t smem_u32(const void* p) {
    uint32_t a;
    asm("{ .reg .u64 t; cvta.to.shared.u64 t, %1; cvt.u32.u64 %0, t; }" : "=r"(a) : "l"(p));
    return a;
}
static __device__ __forceinline__ void cp16(uint32_t dst, const void* src) {
    asm volatile("cp.async.cg.shared.global [%0], [%1], 16;" :: "r"(dst), "l"(src));
}
#define CP_COMMIT() asm volatile("cp.async.commit_group;" ::: "memory")
#define CP_WAIT2()  asm volatile("cp.async.wait_group 2;" ::: "memory")

static __device__ __forceinline__ void ldm4(uint32_t* r, uint32_t addr) {
    asm volatile("ldmatrix.sync.aligned.m8n8.x4.shared.b16 {%0,%1,%2,%3}, [%4];"
                 : "=r"(r[0]), "=r"(r[1]), "=r"(r[2]), "=r"(r[3]) : "r"(addr));
}
static __device__ __forceinline__ void mma16816(float* c, const uint32_t* a, const uint32_t* b) {
    asm volatile(
        "mma.sync.aligned.m16n8k16.row.col.f32.bf16.bf16.f32 "
        "{%0,%1,%2,%3}, {%4,%5,%6,%7}, {%8,%9}, {%0,%1,%2,%3};"
        : "+f"(c[0]), "+f"(c[1]), "+f"(c[2]), "+f"(c[3])
        : "r"(a[0]), "r"(a[1]), "r"(a[2]), "r"(a[3]), "r"(b[0]), "r"(b[1]));
}

// ---------------------------------------------------------------------------
// Split kernels (fp32 -> bf16 hi/lo); W also transposed to (N, K) K-major
// ---------------------------------------------------------------------------
__global__ __launch_bounds__(256) void split_x_kernel(const float* __restrict__ x) {
    int i = blockIdx.x * 256 + threadIdx.x;
    float v = x[i];
    __nv_bfloat16 h = __float2bfloat16(v);
    g_xhi[i] = h;
    g_xlo[i] = __float2bfloat16(v - __bfloat162float(h));
}

// Phase 2 writes 4 consecutive k per thread as one 8B store (conflict-free).
__global__ __launch_bounds__(256) void split_w_kernel(const float* __restrict__ W) {
    __shared__ float t[32][33];           // t[k_local][n_local]
    const int n0 = blockIdx.x * 32, k0 = blockIdx.y * 32;
    const int tx = threadIdx.x & 31, ty = threadIdx.x >> 5;
    #pragma unroll
    for (int j = 0; j < 4; j++)
        t[ty + j * 8][tx] = W[(size_t)(k0 + ty + j * 8) * D_SAE + n0 + tx];
    __syncthreads();

    const int nl = threadIdx.x >> 3;            // 0..31  (n within tile)
    const int kg = (threadIdx.x & 7) * 4;       // 0,4,..28 (k group of 4)
    __nv_bfloat16 hi[4], lo[4];
    #pragma unroll
    for (int e = 0; e < 4; e++) {
        const float v = t[kg + e][nl];
        const __nv_bfloat16 h = __float2bfloat16(v);
        hi[e] = h;
        lo[e] = __float2bfloat16(v - __bfloat162float(h));
    }
    const size_t o = ((size_t)(n0 + nl) * K_DIM + k0 + kg);
    *reinterpret_cast<uint2*>(g_whi + o) = *reinterpret_cast<const uint2*>(hi);
    *reinterpret_cast<uint2*>(g_wlo + o) = *reinterpret_cast<const uint2*>(lo);
}

// ---------------------------------------------------------------------------
// Encode GEMM via mma.sync (HMMA): C = relu(X @ W + b), 3-product bf16 split.
// 128x128 CTA tile, BK=32, 4-stage cp.async pipeline, ONE sync per k-iter.
// bm-fastest grid: A stays L2-resident, B streamed from DRAM once.
// ---------------------------------------------------------------------------
#define LDB     80                       // bytes per 32-element bf16 row (64 + 16 pad)
#define MAT_B   (128 * LDB)              // 10240 bytes per matrix tile
#define A_HI    0
#define A_LO    (MAT_B)
#define B_HI    (2 * MAT_B)
#define B_LO    (3 * MAT_B)
#define STAGE_B (4 * MAT_B)              // 40960
#define STAGES  4
#define NITER   (K_DIM / 32)             // 96
#define SMEM_DYN (STAGES * STAGE_B)      // 163840

static __device__ __forceinline__ void load_stage(
    uint32_t st, const __nv_bfloat16* Ah, const __nv_bfloat16* Al,
    const __nv_bfloat16* Bh, const __nv_bfloat16* Bl, int tid, int k0)
{
    #pragma unroll
    for (int i = 0; i < 2; i++) {
        const int j   = tid + i * 256;       // 0..511
        const int row = j >> 2, seg = j & 3;
        const uint32_t so = row * LDB + seg * 16;
        const size_t   go = (size_t)row * K_DIM + k0 + seg * 8;
        cp16(st + A_HI + so, Ah + go);
        cp16(st + A_LO + so, Al + go);
        cp16(st + B_HI + so, Bh + go);
        cp16(st + B_LO + so, Bl + go);
    }
    CP_COMMIT();
}

__global__ __launch_bounds__(256) void encode_mma_kernel(
    const float* __restrict__ bias, float* __restrict__ C)
{
    extern __shared__ __align__(128) char smem[];
    const uint32_t sb = smem_u32(smem);
    const int tid = threadIdx.x, wid = tid >> 5, lane = tid & 31;
    const int wm = wid >> 2, wn = wid & 3;         // warp grid 2(M) x 4(N)
    const int bm = blockIdx.x, bn = blockIdx.y;    // bm fastest for L2 reuse

    const __nv_bfloat16* Ah = g_xhi + (size_t)bm * 128 * K_DIM;
    const __nv_bfloat16* Al = g_xlo + (size_t)bm * 128 * K_DIM;
    const __nv_bfloat16* Bh = g_whi + (size_t)bn * 128 * K_DIM;
    const __nv_bfloat16* Bl = g_wlo + (size_t)bn * 128 * K_DIM;

    // ldmatrix lane address components
    const uint32_t a_off = (uint32_t)((lane & 15) * LDB + (lane >> 4) * 16);
    const uint32_t b_row = (uint32_t)((lane & 7) + (lane >> 4) * 8);
    const uint32_t b_kh  = (uint32_t)(((lane >> 3) & 1) * 16);

    float acc[4][4][4] = {};

    // Prologue: fill 3 of 4 stages
    for (int s = 0; s < STAGES - 1; s++)
        load_stage(sb + s * STAGE_B, Ah, Al, Bh, Bl, tid, s * 32);

    for (int it = 0; it < NITER; ++it) {
        CP_WAIT2();
        __syncthreads();        // single barrier per iter (4-stage WAR-safe)
        const uint32_t st = sb + (it & 3) * STAGE_B;

        #pragma unroll
        for (int ks = 0; ks < 2; ks++) {
            const uint32_t kb = ks * 32;
            uint32_t ah[4][4], al[4][4], bh[4][2], bl[4][2];
            #pragma unroll
            for (int mt = 0; mt < 4; mt++) {
                const uint32_t r = (wm * 64 + mt * 16) * LDB + a_off + kb;
                ldm4(ah[mt], st + A_HI + r);
                ldm4(al[mt], st + A_LO + r);
            }
            #pragma unroll
            for (int p = 0; p < 2; p++) {
                const uint32_t r = (wn * 32 + p * 16 + b_row) * LDB + b_kh + kb;
                uint32_t t[4];
                ldm4(t, st + B_HI + r);
                bh[2*p][0] = t[0]; bh[2*p][1] = t[1];
                bh[2*p+1][0] = t[2]; bh[2*p+1][1] = t[3];
                ldm4(t, st + B_LO + r);
                bl[2*p][0] = t[0]; bl[2*p][1] = t[1];
                bl[2*p+1][0] = t[2]; bl[2*p+1][1] = t[3];
            }
            // Term-major: 16 independent accs between any accumulator reuse
            #pragma unroll
            for (int mt = 0; mt < 4; mt++)
                #pragma unroll
                for (int nt = 0; nt < 4; nt++)
                    mma16816(acc[mt][nt], ah[mt], bh[nt]);
            #pragma unroll
            for (int mt = 0; mt < 4; mt++)
                #pragma unroll
                for (int nt = 0; nt < 4; nt++)
                    mma16816(acc[mt][nt], ah[mt], bl[nt]);
            #pragma unroll
            for (int mt = 0; mt < 4; mt++)
                #pragma unroll
                for (int nt = 0; nt < 4; nt++)
                    mma16816(acc[mt][nt], al[mt], bh[nt]);
        }
        const int nxt = it + STAGES - 1;
        if (nxt < NITER)
            load_stage(sb + (nxt & 3) * STAGE_B, Ah, Al, Bh, Bl, tid, nxt * 32);
        else
            CP_COMMIT();   // empty group keeps wait_group arithmetic uniform
    }

    // Epilogue: bias + relu, float2 stores
    #pragma unroll
    for (int nt = 0; nt < 4; nt++) {
        const int col = bn * 128 + wn * 32 + nt * 8 + (lane & 3) * 2;
        const float b0 = bias[col], b1 = bias[col + 1];
        #pragma unroll
        for (int mt = 0; mt < 4; mt++) {
            const int row = bm * 128 + wm * 64 + mt * 16 + (lane >> 2);
            float2 v0, v1;
            v0.x = fmaxf(acc[mt][nt][0] + b0, 0.0f);
            v0.y = fmaxf(acc[mt][nt][1] + b1, 0.0f);
            v1.x = fmaxf(acc[mt][nt][2] + b0, 0.0f);
            v1.y = fmaxf(acc[mt][nt][3] + b1, 0.0f);
            *reinterpret_cast<float2*>(C + (size_t)row * D_SAE + col) = v0;
            *reinterpret_cast<float2*>(C + (size_t)(row + 8) * D_SAE + col) = v1;
        }
    }
}

// ---------------------------------------------------------------------------
// Top-64: ONE 11-bit histogram pass (2048 bins, 8KB) + classify + in-smem
// select + narrow refine (topk4 machinery; bin width ~ t/4 -> nc ~ 110).
//  Sweep 1: histogram of (bits>>21)  (values >= 0 post-relu)
//  Sweep 2 (classify): v >= t_hi+dlt certain winner; in [t_lo-dlt, t_hi+dlt)
//    candidate -> smem; else zero. Row fully zeroed except winners.
//  In smem: rank candidates -> t = 64th overall value; > t+dlt winners;
//    |v-t| <= dlt (~0.3/row): exact fp32 recompute + rank (JAX tie-break).
// ---------------------------------------------------------------------------
#define NC_MAX 512
__global__ __launch_bounds__(256) void topk6_kernel(
    float* __restrict__ z, const float* __restrict__ x,
    const float* __restrict__ W, const float* __restrict__ be)
{
    const int b = blockIdx.x, tid = threadIdx.x;
    float* row = z + (size_t)b * D_SAE;
    float4* row4 = reinterpret_cast<float4*>(row);

    __shared__ unsigned int hist[2048];
    __shared__ int chunksum[256];         // reused as `red` in refine phase
    __shared__ float xrow[K_DIM];
    __shared__ int   cidx[NC_MAX];
    __shared__ float cval[NC_MAX];
    __shared__ int   wlist[64];
    __shared__ int sh_chunk, sh_bin, sA, sNC, sNW;
    __shared__ float sT;

    for (int i = tid; i < 2048; i += 256) hist[i] = 0u;
    if (tid == 0) { sA = 0; sNC = 0; sNW = 0; sT = 0.0f; sh_chunk = 0; sh_bin = 0; }
    for (int i = tid; i < K_DIM; i += 256)
        xrow[i] = x[(size_t)b * K_DIM + i];
    __syncthreads();

    // Sweep 1: 11-bit histogram (zeros aggregated locally)
    int zerocnt = 0;
    for (int i = tid; i < D_SAE / 4; i += 256) {
        float4 v = row4[i];
        #pragma unroll
        for (int e = 0; e < 4; e++) {
            const float f = (&v.x)[e];
            if (f > 0.0f) atomicAdd(&hist[__float_as_uint(f) >> 21], 1u);
            else zerocnt++;
        }
    }
    if (zerocnt) atomicAdd(&hist[0], (unsigned)zerocnt);
    __syncthreads();

    // Suffix counts: 8 bins per chunk, then scan over 256 chunks
    {
        int cs = 0;
        #pragma unroll
        for (int j = 0; j < 8; j++) cs += (int)hist[tid * 8 + j];
        chunksum[tid] = cs;
    }
    __syncthreads();
    for (int off = 1; off < 256; off <<= 1) {
        int v = chunksum[tid] + ((tid + off < 256) ? chunksum[tid + off] : 0);
        __syncthreads();
        chunksum[tid] = v;
        __syncthreads();
    }
    {
        int Sc = chunksum[tid];
        int Sn = (tid < 255) ? chunksum[tid + 1] : 0;
        if (Sc >= K_TOP && Sn < K_TOP) sh_chunk = tid;
    }
    __syncthreads();
    if (tid == 0) {
        const int chunk = sh_chunk;
        int cum = (chunk < 255) ? chunksum[chunk + 1] : 0;
        int bin = chunk * 8;
        for (int j = 7; j >= 0; j--) {
            const int h = (int)hist[chunk * 8 + j];
            if (cum + h >= K_TOP) { bin = chunk * 8 + j; break; }
            cum += h;
        }
        sh_bin = bin;
    }
    __syncthreads();

    // 11-bit bin [t_lo, t_hi) of the 64th value
    const unsigned int p11 = (unsigned)sh_bin << 21;
    const float t_lo = __uint_as_float(p11);
    const float t_hi = __uint_as_float(p11 + (1u << 21));
    const float dlt  = 1e-3f * fmaxf(t_lo, 1.0f);       // >> split error ~3e-5
    const float hi_cut = t_hi + dlt;
    const float lo_cut = t_lo - dlt;

    // Sweep 2 (classify): winners kept in row; candidates+losers zeroed
    for (int i = tid; i < D_SAE / 4; i += 256) {
        float4 v = row4[i];
        float4 o = v;
        #pragma unroll
        for (int e = 0; e < 4; e++) {
            const float f = (&v.x)[e];
            if (f >= hi_cut) {
                int s = atomicAdd(&sA, 1);
                g_idx[b * K_TOP + s] = i * 4 + e;
                g_val[b * K_TOP + s] = f;
            } else {
                if (f >= lo_cut && f > 0.0f) {
                    int c = atomicAdd(&sNC, 1);
                    if (c < NC_MAX) { cidx[c] = i * 4 + e; cval[c] = f; }
                }
                (&o.x)[e] = 0.0f;
            }
        }
        row4[i] = o;
    }
    __syncthreads();

    const int A = sA;
    const int nc = (sNC < NC_MAX) ? sNC : NC_MAX;
    const int need = K_TOP - A;          // >= 1 by construction

    // Find t = need-th largest candidate (approx, idx tie-break). nc ~ 110.
    for (int c = tid; c < nc; c += 256) {
        const float vc = cval[c];
        const int id = cidx[c];
        int r = 0;
        for (int j = 0; j < nc; j++) {
            const float vj = cval[j];
            r += (vj > vc) || (vj == vc && cidx[j] < id);
        }
        if (r == need - 1) sT = vc;
    }
    __syncthreads();
    const float t = sT;

    // Candidates clearly above t: certain winners. Window members: refine.
    for (int c = tid; c < nc; c += 256) {
        const float vc = cval[c];
        if (vc > t + dlt) {
            int s = atomicAdd(&sA, 1);
            const int m = cidx[c];
            g_idx[b * K_TOP + s] = m;
            g_val[b * K_TOP + s] = vc;
            row[m] = vc;                 // restore (was zeroed in classify)
        } else if (fabsf(vc - t) <= dlt) {
            int w = atomicAdd(&sNW, 1);
            if (w < 64) wlist[w] = c;
        }
    }
    __syncthreads();

    const int nwin = (sNW < 64) ? sNW : 64;
    const int need2 = K_TOP - sA;        // remaining slots

    if (nwin > 0) {
        float* red = reinterpret_cast<float*>(chunksum);   // reuse (scan done)
        for (int k = 0; k < nwin; k++) {
            const int c = wlist[k];
            const int m = cidx[c];
            float p = 0.0f;
            for (int kk = tid; kk < K_DIM; kk += 256)
                p = fmaf(xrow[kk], W[(size_t)kk * D_SAE + m], p);
            red[tid] = p;
            __syncthreads();
            for (int s = 128; s > 0; s >>= 1) {
                if (tid < s) red[tid] += red[tid + s];
                __syncthreads();
            }
            if (tid == 0) cval[c] = fmaxf(red[0] + be[m], 0.0f);
            __syncthreads();
        }

        if (tid < nwin) {
            const int c = wlist[tid];
            const int m = cidx[c];
            const float vc = cval[c];
            int r = 0;
            for (int j = 0; j < nwin; j++) {
                if (j == tid) continue;
                const int cj = wlist[j];
                const float vj = cval[cj];
                if (vj > vc || (vj == vc && cidx[cj] < m)) r++;
            }
            if (r < need2) {
                row[m] = vc;
                int s = atomicAdd(&sA, 1);
                g_idx[b * K_TOP + s] = m;
                g_val[b * K_TOP + s] = vc;
            }
        }
    }
}

// ---------------------------------------------------------------------------
// Sparse decode (float4): x_hat[b,t,d] = b_dec[t,d] + sum_s val*W_dec[t,m,d]
// ---------------------------------------------------------------------------
__global__ __launch_bounds__(256) void decode_kernel(
    const float* __restrict__ W_dec, const float* __restrict__ b_dec,
    float* __restrict__ xhat)
{
    const int b = blockIdx.x;
    const int tid = threadIdx.x;
    const float4* W4 = reinterpret_cast<const float4*>(W_dec);
    const float4* bd4 = reinterpret_cast<const float4*>(b_dec);

    __shared__ float sv[K_TOP];
    __shared__ int   si[K_TOP];
    if (tid < K_TOP) {
        sv[tid] = g_val[b * K_TOP + tid];
        si[tid] = g_idx[b * K_TOP + tid];
    }

    float4 acc[3];
    size_t off4[3];
    #pragma unroll
    for (int s = 0; s < 3; s++) {
        const int chunk = tid + s * 256;          // 0..767 float4 chunks
        const int t = chunk / 192;
        const int d4 = chunk - t * 192;
        off4[s] = (size_t)t * D_SAE * 192 + d4;
        acc[s] = bd4[chunk];
    }
    __syncthreads();

    #pragma unroll 2
    for (int i = 0; i < K_TOP; i++) {
        const float v = sv[i];
        const size_t mo = (size_t)si[i] * 192;
        #pragma unroll
        for (int s = 0; s < 3; s++) {
            const float4 w = __ldg(W4 + off4[s] + mo);
            acc[s].x = fmaf(v, w.x, acc[s].x);
            acc[s].y = fmaf(v, w.y, acc[s].y);
            acc[s].z = fmaf(v, w.z, acc[s].z);
            acc[s].w = fmaf(v, w.w, acc[s].w);
        }
    }

    float4* out4 = reinterpret_cast<float4*>(xhat + (size_t)b * TD);
    #pragma unroll
    for (int s = 0; s < 3; s++)
        out4[tid + s * 256] = acc[s];
}

// ---------------------------------------------------------------------------
// Launch
// ---------------------------------------------------------------------------
extern "C" void kernel_launch(void* const* d_in, const int* in_sizes, int n_in,
                              void* d_out, int out_size)
{
    const float* x     = (const float*)d_in[0];
    const float* W_enc = (const float*)d_in[1];
    const float* b_enc = (const float*)d_in[2];
    const float* W_dec = (const float*)d_in[3];
    const float* b_dec = (const float*)d_in[4];

    float* xhat = (float*)d_out;
    float* z    = xhat + (size_t)B_SZ * TD;

    static int attr_set = 0;
    if (!attr_set) {
        cudaFuncSetAttribute(encode_mma_kernel,
                             cudaFuncAttributeMaxDynamicSharedMemorySize, SMEM_DYN);
        attr_set = 1;
    }

    split_x_kernel<<<(B_SZ * K_DIM) / 256, 256>>>(x);
    split_w_kernel<<<dim3(D_SAE / 32, K_DIM / 32), 256>>>(W_enc);
    encode_mma_kernel<<<dim3(B_SZ / 128, D_SAE / 128), 256, SMEM_DYN>>>(b_enc, z);
    topk6_kernel<<<B_SZ, 256>>>(z, x, W_enc, b_enc);
    decode_kernel<<<B_SZ, 256>>>(W_dec, b_dec, xhat);
}

// round 14
// speedup vs baseline: 1.0675x; 1.0675x over previous
#include <cuda_runtime.h>
#include <cuda_bf16.h>
#include <cstdint>

// Problem constants
#define B_SZ   1024
#define T_SZ   4
#define D_IN   768
#define D_SAE  16384
#define K_TOP  64
#define K_DIM  3072
#define TD     3072

// ---------------------------------------------------------------------------
// Device scratch (no allocation allowed)
// ---------------------------------------------------------------------------
__device__ __nv_bfloat16 g_xhi[B_SZ * K_DIM];
__device__ __nv_bfloat16 g_xlo[B_SZ * K_DIM];
__device__ __nv_bfloat16 g_whi[(size_t)D_SAE * K_DIM];   // W^T hi, (N, K) row-major
__device__ __nv_bfloat16 g_wlo[(size_t)D_SAE * K_DIM];   // W^T lo
__device__ int   g_idx[B_SZ * K_TOP];
__device__ float g_val[B_SZ * K_TOP];

// ---------------------------------------------------------------------------
// PTX helpers (base sm_80+ features only: cp.async, ldmatrix, mma.sync)
// ---------------------------------------------------------------------------
static __device__ __forceinline__ uint32_t smem_u32(const void* p) {
    uint32_t a;
    asm("{ .reg .u64 t; cvta.to.shared.u64 t, %1; cvt.u32.u64 %0, t; }" : "=r"(a) : "l"(p));
    return a;
}
static __device__ __forceinline__ void cp16(uint32_t dst, const void* src) {
    asm volatile("cp.async.cg.shared.global [%0], [%1], 16;" :: "r"(dst), "l"(src));
}
#define CP_COMMIT() asm volatile("cp.async.commit_group;" ::: "memory")
#define CP_WAIT3()  asm volatile("cp.async.wait_group 3;" ::: "memory")

static __device__ __forceinline__ void ldm4(uint32_t* r, uint32_t addr) {
    asm volatile("ldmatrix.sync.aligned.m8n8.x4.shared.b16 {%0,%1,%2,%3}, [%4];"
                 : "=r"(r[0]), "=r"(r[1]), "=r"(r[2]), "=r"(r[3]) : "r"(addr));
}
static __device__ __forceinline__ void mma16816(float* c, const uint32_t* a, const uint32_t* b) {
    asm volatile(
        "mma.sync.aligned.m16n8k16.row.col.f32.bf16.bf16.f32 "
        "{%0,%1,%2,%3}, {%4,%5,%6,%7}, {%8,%9}, {%0,%1,%2,%3};"
        : "+f"(c[0]), "+f"(c[1]), "+f"(c[2]), "+f"(c[3])
        : "r"(a[0]), "r"(a[1]), "r"(a[2]), "r"(a[3]), "r"(b[0]), "r"(b[1]));
}

// ---------------------------------------------------------------------------
// Split kernels (fp32 -> bf16 hi/lo); W also transposed to (N, K) K-major
// ---------------------------------------------------------------------------
__global__ __launch_bounds__(256) void split_x_kernel(const float* __restrict__ x) {
    int i = blockIdx.x * 256 + threadIdx.x;
    float v = x[i];
    __nv_bfloat16 h = __float2bfloat16(v);
    g_xhi[i] = h;
    g_xlo[i] = __float2bfloat16(v - __bfloat162float(h));
}

// Phase 2 writes 4 consecutive k per thread as one 8B store (conflict-free).
__global__ __launch_bounds__(256) void split_w_kernel(const float* __restrict__ W) {
    __shared__ float t[32][33];           // t[k_local][n_local]
    const int n0 = blockIdx.x * 32, k0 = blockIdx.y * 32;
    const int tx = threadIdx.x & 31, ty = threadIdx.x >> 5;
    #pragma unroll
    for (int j = 0; j < 4; j++)
        t[ty + j * 8][tx] = W[(size_t)(k0 + ty + j * 8) * D_SAE + n0 + tx];
    __syncthreads();

    const int nl = threadIdx.x >> 3;            // 0..31  (n within tile)
    const int kg = (threadIdx.x & 7) * 4;       // 0,4,..28 (k group of 4)
    __nv_bfloat16 hi[4], lo[4];
    #pragma unroll
    for (int e = 0; e < 4; e++) {
        const float v = t[kg + e][nl];
        const __nv_bfloat16 h = __float2bfloat16(v);
        hi[e] = h;
        lo[e] = __float2bfloat16(v - __bfloat162float(h));
    }
    const size_t o = ((size_t)(n0 + nl) * K_DIM + k0 + kg);
    *reinterpret_cast<uint2*>(g_whi + o) = *reinterpret_cast<const uint2*>(hi);
    *reinterpret_cast<uint2*>(g_wlo + o) = *reinterpret_cast<const uint2*>(lo);
}

// ---------------------------------------------------------------------------
// Encode GEMM via mma.sync (HMMA): C = relu(X @ W + b), 3-product bf16 split.
// 128x128 CTA tile, BK=32, FIVE-stage cp.async pipeline (wait_group 3),
// ONE sync per k-iter. Tile it+4 is written into stage (it+4)%5 — the stage
// read in iteration it-1, already drained by this iteration's barrier.
// bm-fastest grid: A L2-resident, B streamed once.
// ---------------------------------------------------------------------------
#define LDB     80                       // bytes per 32-element bf16 row (64 + 16 pad)
#define MAT_B   (128 * LDB)              // 10240 bytes per matrix tile
#define A_HI    0
#define A_LO    (MAT_B)
#define B_HI    (2 * MAT_B)
#define B_LO    (3 * MAT_B)
#define STAGE_B (4 * MAT_B)              // 40960
#define STAGES  5
#define NITER   (K_DIM / 32)             // 96
#define SMEM_DYN (STAGES * STAGE_B)      // 204800

static __device__ __forceinline__ void load_stage(
    uint32_t st, const __nv_bfloat16* Ah, const __nv_bfloat16* Al,
    const __nv_bfloat16* Bh, const __nv_bfloat16* Bl, int tid, int k0)
{
    #pragma unroll
    for (int i = 0; i < 2; i++) {
        const int j   = tid + i * 256;       // 0..511
        const int row = j >> 2, seg = j & 3;
        const uint32_t so = row * LDB + seg * 16;
        const size_t   go = (size_t)row * K_DIM + k0 + seg * 8;
        cp16(st + A_HI + so, Ah + go);
        cp16(st + A_LO + so, Al + go);
        cp16(st + B_HI + so, Bh + go);
        cp16(st + B_LO + so, Bl + go);
    }
    CP_COMMIT();
}

__global__ __launch_bounds__(256) void encode_mma_kernel(
    const float* __restrict__ bias, float* __restrict__ C)
{
    extern __shared__ __align__(128) char smem[];
    const uint32_t sb = smem_u32(smem);
    const int tid = threadIdx.x, wid = tid >> 5, lane = tid & 31;
    const int wm = wid >> 2, wn = wid & 3;         // warp grid 2(M) x 4(N)
    const int bm = blockIdx.x, bn = blockIdx.y;    // bm fastest for L2 reuse

    const __nv_bfloat16* Ah = g_xhi + (size_t)bm * 128 * K_DIM;
    const __nv_bfloat16* Al = g_xlo + (size_t)bm * 128 * K_DIM;
    const __nv_bfloat16* Bh = g_whi + (size_t)bn * 128 * K_DIM;
    const __nv_bfloat16* Bl = g_wlo + (size_t)bn * 128 * K_DIM;

    // ldmatrix lane address components
    const uint32_t a_off = (uint32_t)((lane & 15) * LDB + (lane >> 4) * 16);
    const uint32_t b_row = (uint32_t)((lane & 7) + (lane >> 4) * 8);
    const uint32_t b_kh  = (uint32_t)(((lane >> 3) & 1) * 16);

    float acc[4][4][4] = {};

    // Prologue: fill 4 of 5 stages (tiles 0..3 -> stages 0..3)
    for (int s = 0; s < STAGES - 1; s++)
        load_stage(sb + s * STAGE_B, Ah, Al, Bh, Bl, tid, s * 32);

    int stage_rd = 0;   // = it % 5
    int stage_wr = 4;   // = (it + 4) % 5
    for (int it = 0; it < NITER; ++it) {
        CP_WAIT3();
        __syncthreads();        // single barrier per iter (5-stage WAR-safe)
        const uint32_t st = sb + stage_rd * STAGE_B;

        #pragma unroll
        for (int ks = 0; ks < 2; ks++) {
            const uint32_t kb = ks * 32;
            uint32_t ah[4][4], al[4][4], bh[4][2], bl[4][2];
            #pragma unroll
            for (int mt = 0; mt < 4; mt++) {
                const uint32_t r = (wm * 64 + mt * 16) * LDB + a_off + kb;
                ldm4(ah[mt], st + A_HI + r);
                ldm4(al[mt], st + A_LO + r);
            }
            #pragma unroll
            for (int p = 0; p < 2; p++) {
                const uint32_t r = (wn * 32 + p * 16 + b_row) * LDB + b_kh + kb;
                uint32_t t[4];
                ldm4(t, st + B_HI + r);
                bh[2*p][0] = t[0]; bh[2*p][1] = t[1];
                bh[2*p+1][0] = t[2]; bh[2*p+1][1] = t[3];
                ldm4(t, st + B_LO + r);
                bl[2*p][0] = t[0]; bl[2*p][1] = t[1];
                bl[2*p+1][0] = t[2]; bl[2*p+1][1] = t[3];
            }
            // Term-major: 16 independent accs between any accumulator reuse
            #pragma unroll
            for (int mt = 0; mt < 4; mt++)
                #pragma unroll
                for (int nt = 0; nt < 4; nt++)
                    mma16816(acc[mt][nt], ah[mt], bh[nt]);
            #pragma unroll
            for (int mt = 0; mt < 4; mt++)
                #pragma unroll
                for (int nt = 0; nt < 4; nt++)
                    mma16816(acc[mt][nt], ah[mt], bl[nt]);
            #pragma unroll
            for (int mt = 0; mt < 4; mt++)
                #pragma unroll
                for (int nt = 0; nt < 4; nt++)
                    mma16816(acc[mt][nt], al[mt], bh[nt]);
        }
        const int nxt = it + STAGES - 1;
        if (nxt < NITER)
            load_stage(sb + stage_wr * STAGE_B, Ah, Al, Bh, Bl, tid, nxt * 32);
        else
            CP_COMMIT();   // empty group keeps wait_group arithmetic uniform
        stage_rd = (stage_rd == STAGES - 1) ? 0 : stage_rd + 1;
        stage_wr = (stage_wr == STAGES - 1) ? 0 : stage_wr + 1;
    }

    // Epilogue: bias + relu, float2 stores
    #pragma unroll
    for (int nt = 0; nt < 4; nt++) {
        const int col = bn * 128 + wn * 32 + nt * 8 + (lane & 3) * 2;
        const float b0 = bias[col], b1 = bias[col + 1];
        #pragma unroll
        for (int mt = 0; mt < 4; mt++) {
            const int row = bm * 128 + wm * 64 + mt * 16 + (lane >> 2);
            float2 v0, v1;
            v0.x = fmaxf(acc[mt][nt][0] + b0, 0.0f);
            v0.y = fmaxf(acc[mt][nt][1] + b1, 0.0f);
            v1.x = fmaxf(acc[mt][nt][2] + b0, 0.0f);
            v1.y = fmaxf(acc[mt][nt][3] + b1, 0.0f);
            *reinterpret_cast<float2*>(C + (size_t)row * D_SAE + col) = v0;
            *reinterpret_cast<float2*>(C + (size_t)(row + 8) * D_SAE + col) = v1;
        }
    }
}

// ---------------------------------------------------------------------------
// Top-64 (topk4, R9-proven, 143us): 2-pass radix (16-bit bin) + in-smem exact
// select + NARROW refine.
// ---------------------------------------------------------------------------
#define NC_MAX 256
__global__ __launch_bounds__(256) void topk4_kernel(
    float* __restrict__ z, const float* __restrict__ x,
    const float* __restrict__ W, const float* __restrict__ be)
{
    const int b = blockIdx.x, tid = threadIdx.x;
    float* row = z + (size_t)b * D_SAE;
    float4* row4 = reinterpret_cast<float4*>(row);

    __shared__ float xrow[K_DIM];
    __shared__ unsigned int hist[256];
    __shared__ unsigned int sh_prefix;
    __shared__ int sh_kRemain;
    __shared__ int sA, sNC, sNW;
    __shared__ float sT;
    __shared__ int   cidx[NC_MAX];
    __shared__ float cval[NC_MAX];
    __shared__ int   wlist[64];
    __shared__ float red[256];

    for (int i = tid; i < K_DIM; i += 256)
        xrow[i] = x[(size_t)b * K_DIM + i];

    if (tid == 0) { sh_prefix = 0u; sh_kRemain = K_TOP; sA = 0; sNC = 0; sNW = 0; sT = 0.0f; }
    __syncthreads();

    // 2-pass radix select on top 16 bits (values >= 0 post-relu)
    #pragma unroll
    for (int shift = 24; shift >= 16; shift -= 8) {
        hist[tid] = 0u;
        __syncthreads();
        const unsigned int prefix = sh_prefix;
        const unsigned int hmask = (shift == 24) ? 0u : 0xFF000000u;
        for (int i = tid; i < D_SAE / 4; i += 256) {
            float4 v = row4[i];
            #pragma unroll
            for (int e = 0; e < 4; e++) {
                unsigned int bits = __float_as_uint((&v.x)[e]);
                if ((bits & hmask) == prefix)
                    atomicAdd(&hist[(bits >> shift) & 0xFF], 1u);
            }
        }
        __syncthreads();
        if (tid == 0) {
            int cum = 0;
            const int kr = sh_kRemain;
            for (int bin = 255; bin >= 0; bin--) {
                cum += (int)hist[bin];
                if (cum >= kr) {
                    sh_kRemain = kr - (cum - (int)hist[bin]);
                    sh_prefix = prefix | ((unsigned int)bin << shift);
                    break;
                }
            }
        }
        __syncthreads();
    }

    // 16-bit bin [t_lo, t_hi) of the 64th value
    const unsigned int p16 = sh_prefix;
    const float t_lo = __uint_as_float(p16);
    const float t_hi = __uint_as_float(p16 + 0x10000u);
    const float dlt  = 1e-3f * fmaxf(t_lo, 1.0f);       // >> split error ~3e-5
    const float hi_cut = t_hi + dlt;
    const float lo_cut = t_lo - dlt;

    // Classify sweep (float4): winners kept in row; candidates+losers zeroed
    for (int i = tid; i < D_SAE / 4; i += 256) {
        float4 v = row4[i];
        float4 o = v;
        #pragma unroll
        for (int e = 0; e < 4; e++) {
            const float f = (&v.x)[e];
            if (f >= hi_cut) {
                int s = atomicAdd(&sA, 1);
                g_idx[b * K_TOP + s] = i * 4 + e;
                g_val[b * K_TOP + s] = f;
            } else {
                if (f >= lo_cut && f > 0.0f) {
                    int c = atomicAdd(&sNC, 1);
                    if (c < NC_MAX) { cidx[c] = i * 4 + e; cval[c] = f; }
                }
                (&o.x)[e] = 0.0f;
            }
        }
        row4[i] = o;
    }
    __syncthreads();

    const int A = sA;
    const int nc = (sNC < NC_MAX) ? sNC : NC_MAX;
    const int need = K_TOP - A;          // >= 1 by construction

    // Find t = need-th largest candidate (approx, idx tie-break). nc ~ 10.
    for (int c = tid; c < nc; c += 256) {
        const float vc = cval[c];
        const int id = cidx[c];
        int r = 0;
        for (int j = 0; j < nc; j++) {
            const float vj = cval[j];
            r += (vj > vc) || (vj == vc && cidx[j] < id);
        }
        if (r == need - 1) sT = vc;
    }
    __syncthreads();
    const float t = sT;

    // Candidates clearly above t: certain winners (approx values). Window: refine.
    for (int c = tid; c < nc; c += 256) {
        const float vc = cval[c];
        if (vc > t + dlt) {
            int s = atomicAdd(&sA, 1);
            const int m = cidx[c];
            g_idx[b * K_TOP + s] = m;
            g_val[b * K_TOP + s] = vc;
            row[m] = vc;                 // restore (was zeroed in classify)
        } else if (fabsf(vc - t) <= dlt) {
            int w = atomicAdd(&sNW, 1);
            if (w < 64) wlist[w] = c;
        }
    }
    __syncthreads();

    const int nwin = (sNW < 64) ? sNW : 64;
    const int need2 = K_TOP - sA;        // remaining slots for window members

    if (nwin > 0) {
        // Exact fp32 recompute of window members (rare: ~0.3/row)
        for (int k = 0; k < nwin; k++) {
            const int c = wlist[k];
            const int m = cidx[c];
            float p = 0.0f;
            for (int kk = tid; kk < K_DIM; kk += 256)
                p = fmaf(xrow[kk], W[(size_t)kk * D_SAE + m], p);
            red[tid] = p;
            __syncthreads();
            for (int s = 128; s > 0; s >>= 1) {
                if (tid < s) red[tid] += red[tid + s];
                __syncthreads();
            }
            if (tid == 0) cval[c] = fmaxf(red[0] + be[m], 0.0f);
            __syncthreads();
        }

        // Rank window members by exact value (desc, idx asc); keep top need2
        if (tid < nwin) {
            const int c = wlist[tid];
            const int m = cidx[c];
            const float vc = cval[c];
            int r = 0;
            for (int j = 0; j < nwin; j++) {
                if (j == tid) continue;
                const int cj = wlist[j];
                const float vj = cval[cj];
                if (vj > vc || (vj == vc && cidx[cj] < m)) r++;
            }
            if (r < need2) {
                row[m] = vc;
                int s = atomicAdd(&sA, 1);
                g_idx[b * K_TOP + s] = m;
                g_val[b * K_TOP + s] = vc;
            }
        }
    }
}

// ---------------------------------------------------------------------------
// Sparse decode (float4): x_hat[b,t,d] = b_dec[t,d] + sum_s val*W_dec[t,m,d]
// ---------------------------------------------------------------------------
__global__ __launch_bounds__(256) void decode_kernel(
    const float* __restrict__ W_dec, const float* __restrict__ b_dec,
    float* __restrict__ xhat)
{
    const int b = blockIdx.x;
    const int tid = threadIdx.x;
    const float4* W4 = reinterpret_cast<const float4*>(W_dec);
    const float4* bd4 = reinterpret_cast<const float4*>(b_dec);

    __shared__ float sv[K_TOP];
    __shared__ int   si[K_TOP];
    if (tid < K_TOP) {
        sv[tid] = g_val[b * K_TOP + tid];
        si[tid] = g_idx[b * K_TOP + tid];
    }

    float4 acc[3];
    size_t off4[3];
    #pragma unroll
    for (int s = 0; s < 3; s++) {
        const int chunk = tid + s * 256;          // 0..767 float4 chunks
        const int t = chunk / 192;
        const int d4 = chunk - t * 192;
        off4[s] = (size_t)t * D_SAE * 192 + d4;
        acc[s] = bd4[chunk];
    }
    __syncthreads();

    #pragma unroll 2
    for (int i = 0; i < K_TOP; i++) {
        const float v = sv[i];
        const size_t mo = (size_t)si[i] * 192;
        #pragma unroll
        for (int s = 0; s < 3; s++) {
            const float4 w = __ldg(W4 + off4[s] + mo);
            acc[s].x = fmaf(v, w.x, acc[s].x);
            acc[s].y = fmaf(v, w.y, acc[s].y);
            acc[s].z = fmaf(v, w.z, acc[s].z);
            acc[s].w = fmaf(v, w.w, acc[s].w);
        }
    }

    float4* out4 = reinterpret_cast<float4*>(xhat + (size_t)b * TD);
    #pragma unroll
    for (int s = 0; s < 3; s++)
        out4[tid + s * 256] = acc[s];
}

// ---------------------------------------------------------------------------
// Launch
// ---------------------------------------------------------------------------
extern "C" void kernel_launch(void* const* d_in, const int* in_sizes, int n_in,
                              void* d_out, int out_size)
{
    const float* x     = (const float*)d_in[0];
    const float* W_enc = (const float*)d_in[1];
    const float* b_enc = (const float*)d_in[2];
    const float* W_dec = (const float*)d_in[3];
    const float* b_dec = (const float*)d_in[4];

    float* xhat = (float*)d_out;
    float* z    = xhat + (size_t)B_SZ * TD;

    static int attr_set = 0;
    if (!attr_set) {
        cudaFuncSetAttribute(encode_mma_kernel,
                             cudaFuncAttributeMaxDynamicSharedMemorySize, SMEM_DYN);
        attr_set = 1;
    }

    split_x_kernel<<<(B_SZ * K_DIM) / 256, 256>>>(x);
    split_w_kernel<<<dim3(D_SAE / 32, K_DIM / 32), 256>>>(W_enc);
    encode_mma_kernel<<<dim3(B_SZ / 128, D_SAE / 128), 256, SMEM_DYN>>>(b_enc, z);
    topk4_kernel<<<B_SZ, 256>>>(z, x, W_enc, b_enc);
    decode_kernel<<<B_SZ, 256>>>(W_dec, b_dec, xhat);
}

// round 15
// speedup vs baseline: 1.0870x; 1.0183x over previous
#include <cuda_runtime.h>
#include <cuda_bf16.h>
#include <cstdint>

// Problem constants
#define B_SZ   1024
#define T_SZ   4
#define D_IN   768
#define D_SAE  16384
#define K_TOP  64
#define K_DIM  3072
#define TD     3072

// ---------------------------------------------------------------------------
// Device scratch (no allocation allowed)
// ---------------------------------------------------------------------------
__device__ __nv_bfloat16 g_xhi[B_SZ * K_DIM];
__device__ __nv_bfloat16 g_xlo[B_SZ * K_DIM];
__device__ __nv_bfloat16 g_whi[(size_t)D_SAE * K_DIM];   // W^T hi, (N, K) row-major
__device__ __nv_bfloat16 g_wlo[(size_t)D_SAE * K_DIM];   // W^T lo
__device__ int   g_idx[B_SZ * K_TOP];
__device__ float g_val[B_SZ * K_TOP];

// ---------------------------------------------------------------------------
// PTX helpers (base sm_80+ features only: cp.async, ldmatrix, mma.sync)
// ---------------------------------------------------------------------------
static __device__ __forceinline__ uint32_t smem_u32(const void* p) {
    uint32_t a;
    asm("{ .reg .u64 t; cvta.to.shared.u64 t, %1; cvt.u32.u64 %0, t; }" : "=r"(a) : "l"(p));
    return a;
}
static __device__ __forceinline__ void cp16(uint32_t dst, const void* src) {
    asm volatile("cp.async.cg.shared.global [%0], [%1], 16;" :: "r"(dst), "l"(src));
}
#define CP_COMMIT() asm volatile("cp.async.commit_group;" ::: "memory")
#define CP_WAIT1()  asm volatile("cp.async.wait_group 1;" ::: "memory")

static __device__ __forceinline__ void ldm4(uint32_t* r, uint32_t addr) {
    asm volatile("ldmatrix.sync.aligned.m8n8.x4.shared.b16 {%0,%1,%2,%3}, [%4];"
                 : "=r"(r[0]), "=r"(r[1]), "=r"(r[2]), "=r"(r[3]) : "r"(addr));
}
static __device__ __forceinline__ void mma16816(float* c, const uint32_t* a, const uint32_t* b) {
    asm volatile(
        "mma.sync.aligned.m16n8k16.row.col.f32.bf16.bf16.f32 "
        "{%0,%1,%2,%3}, {%4,%5,%6,%7}, {%8,%9}, {%0,%1,%2,%3};"
        : "+f"(c[0]), "+f"(c[1]), "+f"(c[2]), "+f"(c[3])
        : "r"(a[0]), "r"(a[1]), "r"(a[2]), "r"(a[3]), "r"(b[0]), "r"(b[1]));
}

// ---------------------------------------------------------------------------
// Split kernels (fp32 -> bf16 hi/lo); W also transposed to (N, K) K-major
// ---------------------------------------------------------------------------
__global__ __launch_bounds__(256) void split_x_kernel(const float* __restrict__ x) {
    int i = blockIdx.x * 256 + threadIdx.x;
    float v = x[i];
    __nv_bfloat16 h = __float2bfloat16(v);
    g_xhi[i] = h;
    g_xlo[i] = __float2bfloat16(v - __bfloat162float(h));
}

// Phase 2 writes 4 consecutive k per thread as one 8B store (conflict-free).
__global__ __launch_bounds__(256) void split_w_kernel(const float* __restrict__ W) {
    __shared__ float t[32][33];           // t[k_local][n_local]
    const int n0 = blockIdx.x * 32, k0 = blockIdx.y * 32;
    const int tx = threadIdx.x & 31, ty = threadIdx.x >> 5;
    #pragma unroll
    for (int j = 0; j < 4; j++)
        t[ty + j * 8][tx] = W[(size_t)(k0 + ty + j * 8) * D_SAE + n0 + tx];
    __syncthreads();

    const int nl = threadIdx.x >> 3;            // 0..31  (n within tile)
    const int kg = (threadIdx.x & 7) * 4;       // 0,4,..28 (k group of 4)
    __nv_bfloat16 hi[4], lo[4];
    #pragma unroll
    for (int e = 0; e < 4; e++) {
        const float v = t[kg + e][nl];
        const __nv_bfloat16 h = __float2bfloat16(v);
        hi[e] = h;
        lo[e] = __float2bfloat16(v - __bfloat162float(h));
    }
    const size_t o = ((size_t)(n0 + nl) * K_DIM + k0 + kg);
    *reinterpret_cast<uint2*>(g_whi + o) = *reinterpret_cast<const uint2*>(hi);
    *reinterpret_cast<uint2*>(g_wlo + o) = *reinterpret_cast<const uint2*>(lo);
}

// ---------------------------------------------------------------------------
// Encode GEMM via mma.sync (HMMA): C = relu(X @ W + b), 3-product bf16 split.
// 128x256 CTA tile, 8 warps of 64x64 (smem-traffic-optimal), BK=32,
// 3-stage cp.async pipeline (wait_group 1), ONE sync per k-iter.
// bm-fastest grid: A L2-resident, B streamed from DRAM once.
// ---------------------------------------------------------------------------
#define LDB     80                       // bytes per 32-element bf16 row (64 + 16 pad)
#define A_ROWS  128
#define B_ROWS  256
#define A_TILE  (A_ROWS * LDB)           // 10240
#define B_TILE  (B_ROWS * LDB)           // 20480
#define A_HI    0
#define A_LO    (A_TILE)
#define B_HI    (2 * A_TILE)
#define B_LO    (2 * A_TILE + B_TILE)
#define STAGE_B (2 * A_TILE + 2 * B_TILE)   // 61440
#define STAGES  3
#define NITER   (K_DIM / 32)             // 96
#define SMEM_DYN (STAGES * STAGE_B)      // 184320

static __device__ __forceinline__ void load_stage(
    uint32_t st, const __nv_bfloat16* Ah, const __nv_bfloat16* Al,
    const __nv_bfloat16* Bh, const __nv_bfloat16* Bl, int tid, int k0)
{
    // A tiles: 512 chunks each; B tiles: 1024 chunks each (16B chunks)
    #pragma unroll
    for (int i = 0; i < 2; i++) {                 // Ah + Al
        const int j = tid + i * 256;              // 0..511
        const int row = j >> 2, seg = j & 3;
        const uint32_t so = row * LDB + seg * 16;
        const size_t   go = (size_t)row * K_DIM + k0 + seg * 8;
        cp16(st + A_HI + so, Ah + go);
        cp16(st + A_LO + so, Al + go);
    }
    #pragma unroll
    for (int i = 0; i < 4; i++) {                 // Bh + Bl
        const int j = tid + i * 256;              // 0..1023
        const int row = j >> 2, seg = j & 3;
        const uint32_t so = row * LDB + seg * 16;
        const size_t   go = (size_t)row * K_DIM + k0 + seg * 8;
        cp16(st + B_HI + so, Bh + go);
        cp16(st + B_LO + so, Bl + go);
    }
    CP_COMMIT();
}

__global__ __launch_bounds__(256, 1) void encode_mma_kernel(
    const float* __restrict__ bias, float* __restrict__ C)
{
    extern __shared__ __align__(128) char smem[];
    const uint32_t sb = smem_u32(smem);
    const int tid = threadIdx.x, wid = tid >> 5, lane = tid & 31;
    const int wm = wid >> 2, wn = wid & 3;         // warp grid 2(M) x 4(N), 64x64 tiles
    const int bm = blockIdx.x, bn = blockIdx.y;    // bm fastest for L2 reuse

    const __nv_bfloat16* Ah = g_xhi + (size_t)bm * 128 * K_DIM;
    const __nv_bfloat16* Al = g_xlo + (size_t)bm * 128 * K_DIM;
    const __nv_bfloat16* Bh = g_whi + (size_t)bn * 256 * K_DIM;
    const __nv_bfloat16* Bl = g_wlo + (size_t)bn * 256 * K_DIM;

    // ldmatrix lane address components
    const uint32_t a_off = (uint32_t)((lane & 15) * LDB + (lane >> 4) * 16);
    const uint32_t b_row = (uint32_t)((lane & 7) + (lane >> 4) * 8);
    const uint32_t b_kh  = (uint32_t)(((lane >> 3) & 1) * 16);

    float acc[4][8][4] = {};    // 4 mt x 8 nt x 4 = 128 regs

    // Prologue: fill 2 of 3 stages (tiles 0,1 -> stages 0,1)
    for (int s = 0; s < STAGES - 1; s++)
        load_stage(sb + s * STAGE_B, Ah, Al, Bh, Bl, tid, s * 32);

    int stage_rd = 0;   // = it % 3
    int stage_wr = 2;   // = (it + 2) % 3
    for (int it = 0; it < NITER; ++it) {
        CP_WAIT1();
        __syncthreads();        // single barrier per iter (3-stage WAR-safe)
        const uint32_t st = sb + stage_rd * STAGE_B;

        #pragma unroll
        for (int ks = 0; ks < 2; ks++) {
            const uint32_t kb = ks * 32;
            uint32_t ah[4][4], al[4][4], bh[8][2], bl[8][2];
            #pragma unroll
            for (int mt = 0; mt < 4; mt++) {
                const uint32_t r = (wm * 64 + mt * 16) * LDB + a_off + kb;
                ldm4(ah[mt], st + A_HI + r);
                ldm4(al[mt], st + A_LO + r);
            }
            #pragma unroll
            for (int p = 0; p < 4; p++) {
                const uint32_t r = (wn * 64 + p * 16 + b_row) * LDB + b_kh + kb;
                uint32_t t[4];
                ldm4(t, st + B_HI + r);
                bh[2*p][0] = t[0]; bh[2*p][1] = t[1];
                bh[2*p+1][0] = t[2]; bh[2*p+1][1] = t[3];
                ldm4(t, st + B_LO + r);
                bl[2*p][0] = t[0]; bl[2*p][1] = t[1];
                bl[2*p+1][0] = t[2]; bl[2*p+1][1] = t[3];
            }
            // Term-major: 32 independent accs between any accumulator reuse
            #pragma unroll
            for (int mt = 0; mt < 4; mt++)
                #pragma unroll
                for (int nt = 0; nt < 8; nt++)
                    mma16816(acc[mt][nt], ah[mt], bh[nt]);
            #pragma unroll
            for (int mt = 0; mt < 4; mt++)
                #pragma unroll
                for (int nt = 0; nt < 8; nt++)
                    mma16816(acc[mt][nt], ah[mt], bl[nt]);
            #pragma unroll
            for (int mt = 0; mt < 4; mt++)
                #pragma unroll
                for (int nt = 0; nt < 8; nt++)
                    mma16816(acc[mt][nt], al[mt], bh[nt]);
        }
        const int nxt = it + STAGES - 1;
        if (nxt < NITER)
            load_stage(sb + stage_wr * STAGE_B, Ah, Al, Bh, Bl, tid, nxt * 32);
        else
            CP_COMMIT();   // empty group keeps wait_group arithmetic uniform
        stage_rd = (stage_rd == STAGES - 1) ? 0 : stage_rd + 1;
        stage_wr = (stage_wr == STAGES - 1) ? 0 : stage_wr + 1;
    }

    // Epilogue: bias + relu, float2 stores
    #pragma unroll
    for (int nt = 0; nt < 8; nt++) {
        const int col = bn * 256 + wn * 64 + nt * 8 + (lane & 3) * 2;
        const float b0 = bias[col], b1 = bias[col + 1];
        #pragma unroll
        for (int mt = 0; mt < 4; mt++) {
            const int row = bm * 128 + wm * 64 + mt * 16 + (lane >> 2);
            float2 v0, v1;
            v0.x = fmaxf(acc[mt][nt][0] + b0, 0.0f);
            v0.y = fmaxf(acc[mt][nt][1] + b1, 0.0f);
            v1.x = fmaxf(acc[mt][nt][2] + b0, 0.0f);
            v1.y = fmaxf(acc[mt][nt][3] + b1, 0.0f);
            *reinterpret_cast<float2*>(C + (size_t)row * D_SAE + col) = v0;
            *reinterpret_cast<float2*>(C + (size_t)(row + 8) * D_SAE + col) = v1;
        }
    }
}

// ---------------------------------------------------------------------------
// Top-64 (topk4, R9-proven, 143us): 2-pass radix (16-bit bin) + in-smem exact
// select + NARROW refine.
// ---------------------------------------------------------------------------
#define NC_MAX 256
__global__ __launch_bounds__(256) void topk4_kernel(
    float* __restrict__ z, const float* __restrict__ x,
    const float* __restrict__ W, const float* __restrict__ be)
{
    const int b = blockIdx.x, tid = threadIdx.x;
    float* row = z + (size_t)b * D_SAE;
    float4* row4 = reinterpret_cast<float4*>(row);

    __shared__ float xrow[K_DIM];
    __shared__ unsigned int hist[256];
    __shared__ unsigned int sh_prefix;
    __shared__ int sh_kRemain;
    __shared__ int sA, sNC, sNW;
    __shared__ float sT;
    __shared__ int   cidx[NC_MAX];
    __shared__ float cval[NC_MAX];
    __shared__ int   wlist[64];
    __shared__ float red[256];

    for (int i = tid; i < K_DIM; i += 256)
        xrow[i] = x[(size_t)b * K_DIM + i];

    if (tid == 0) { sh_prefix = 0u; sh_kRemain = K_TOP; sA = 0; sNC = 0; sNW = 0; sT = 0.0f; }
    __syncthreads();

    // 2-pass radix select on top 16 bits (values >= 0 post-relu)
    #pragma unroll
    for (int shift = 24; shift >= 16; shift -= 8) {
        hist[tid] = 0u;
        __syncthreads();
        const unsigned int prefix = sh_prefix;
        const unsigned int hmask = (shift == 24) ? 0u : 0xFF000000u;
        for (int i = tid; i < D_SAE / 4; i += 256) {
            float4 v = row4[i];
            #pragma unroll
            for (int e = 0; e < 4; e++) {
                unsigned int bits = __float_as_uint((&v.x)[e]);
                if ((bits & hmask) == prefix)
                    atomicAdd(&hist[(bits >> shift) & 0xFF], 1u);
            }
        }
        __syncthreads();
        if (tid == 0) {
            int cum = 0;
            const int kr = sh_kRemain;
            for (int bin = 255; bin >= 0; bin--) {
                cum += (int)hist[bin];
                if (cum >= kr) {
                    sh_kRemain = kr - (cum - (int)hist[bin]);
                    sh_prefix = prefix | ((unsigned int)bin << shift);
                    break;
                }
            }
        }
        __syncthreads();
    }

    // 16-bit bin [t_lo, t_hi) of the 64th value
    const unsigned int p16 = sh_prefix;
    const float t_lo = __uint_as_float(p16);
    const float t_hi = __uint_as_float(p16 + 0x10000u);
    const float dlt  = 1e-3f * fmaxf(t_lo, 1.0f);       // >> split error ~3e-5
    const float hi_cut = t_hi + dlt;
    const float lo_cut = t_lo - dlt;

    // Classify sweep (float4): winners kept in row; candidates+losers zeroed
    for (int i = tid; i < D_SAE / 4; i += 256) {
        float4 v = row4[i];
        float4 o = v;
        #pragma unroll
        for (int e = 0; e < 4; e++) {
            const float f = (&v.x)[e];
            if (f >= hi_cut) {
                int s = atomicAdd(&sA, 1);
                g_idx[b * K_TOP + s] = i * 4 + e;
                g_val[b * K_TOP + s] = f;
            } else {
                if (f >= lo_cut && f > 0.0f) {
                    int c = atomicAdd(&sNC, 1);
                    if (c < NC_MAX) { cidx[c] = i * 4 + e; cval[c] = f; }
                }
                (&o.x)[e] = 0.0f;
            }
        }
        row4[i] = o;
    }
    __syncthreads();

    const int A = sA;
    const int nc = (sNC < NC_MAX) ? sNC : NC_MAX;
    const int need = K_TOP - A;          // >= 1 by construction

    // Find t = need-th largest candidate (approx, idx tie-break). nc ~ 10.
    for (int c = tid; c < nc; c += 256) {
        const float vc = cval[c];
        const int id = cidx[c];
        int r = 0;
        for (int j = 0; j < nc; j++) {
            const float vj = cval[j];
            r += (vj > vc) || (vj == vc && cidx[j] < id);
        }
        if (r == need - 1) sT = vc;
    }
    __syncthreads();
    const float t = sT;

    // Candidates clearly above t: certain winners (approx values). Window: refine.
    for (int c = tid; c < nc; c += 256) {
        const float vc = cval[c];
        if (vc > t + dlt) {
            int s = atomicAdd(&sA, 1);
            const int m = cidx[c];
            g_idx[b * K_TOP + s] = m;
            g_val[b * K_TOP + s] = vc;
            row[m] = vc;                 // restore (was zeroed in classify)
        } else if (fabsf(vc - t) <= dlt) {
            int w = atomicAdd(&sNW, 1);
            if (w < 64) wlist[w] = c;
        }
    }
    __syncthreads();

    const int nwin = (sNW < 64) ? sNW : 64;
    const int need2 = K_TOP - sA;        // remaining slots for window members

    if (nwin > 0) {
        // Exact fp32 recompute of window members (rare: ~0.3/row)
        for (int k = 0; k < nwin; k++) {
            const int c = wlist[k];
            const int m = cidx[c];
            float p = 0.0f;
            for (int kk = tid; kk < K_DIM; kk += 256)
                p = fmaf(xrow[kk], W[(size_t)kk * D_SAE + m], p);
            red[tid] = p;
            __syncthreads();
            for (int s = 128; s > 0; s >>= 1) {
                if (tid < s) red[tid] += red[tid + s];
                __syncthreads();
            }
            if (tid == 0) cval[c] = fmaxf(red[0] + be[m], 0.0f);
            __syncthreads();
        }

        // Rank window members by exact value (desc, idx asc); keep top need2
        if (tid < nwin) {
            const int c = wlist[tid];
            const int m = cidx[c];
            const float vc = cval[c];
            int r = 0;
            for (int j = 0; j < nwin; j++) {
                if (j == tid) continue;
                const int cj = wlist[j];
                const float vj = cval[cj];
                if (vj > vc || (vj == vc && cidx[cj] < m)) r++;
            }
            if (r < need2) {
                row[m] = vc;
                int s = atomicAdd(&sA, 1);
                g_idx[b * K_TOP + s] = m;
                g_val[b * K_TOP + s] = vc;
            }
        }
    }
}

// ---------------------------------------------------------------------------
// Sparse decode (float4): x_hat[b,t,d] = b_dec[t,d] + sum_s val*W_dec[t,m,d]
// ---------------------------------------------------------------------------
__global__ __launch_bounds__(256) void decode_kernel(
    const float* __restrict__ W_dec, const float* __restrict__ b_dec,
    float* __restrict__ xhat)
{
    const int b = blockIdx.x;
    const int tid = threadIdx.x;
    const float4* W4 = reinterpret_cast<const float4*>(W_dec);
    const float4* bd4 = reinterpret_cast<const float4*>(b_dec);

    __shared__ float sv[K_TOP];
    __shared__ int   si[K_TOP];
    if (tid < K_TOP) {
        sv[tid] = g_val[b * K_TOP + tid];
        si[tid] = g_idx[b * K_TOP + tid];
    }

    float4 acc[3];
    size_t off4[3];
    #pragma unroll
    for (int s = 0; s < 3; s++) {
        const int chunk = tid + s * 256;          // 0..767 float4 chunks
        const int t = chunk / 192;
        const int d4 = chunk - t * 192;
        off4[s] = (size_t)t * D_SAE * 192 + d4;
        acc[s] = bd4[chunk];
    }
    __syncthreads();

    #pragma unroll 2
    for (int i = 0; i < K_TOP; i++) {
        const float v = sv[i];
        const size_t mo = (size_t)si[i] * 192;
        #pragma unroll
        for (int s = 0; s < 3; s++) {
            const float4 w = __ldg(W4 + off4[s] + mo);
            acc[s].x = fmaf(v, w.x, acc[s].x);
            acc[s].y = fmaf(v, w.y, acc[s].y);
            acc[s].z = fmaf(v, w.z, acc[s].z);
            acc[s].w = fmaf(v, w.w, acc[s].w);
        }
    }

    float4* out4 = reinterpret_cast<float4*>(xhat + (size_t)b * TD);
    #pragma unroll
    for (int s = 0; s < 3; s++)
        out4[tid + s * 256] = acc[s];
}

// ---------------------------------------------------------------------------
// Launch
// ---------------------------------------------------------------------------
extern "C" void kernel_launch(void* const* d_in, const int* in_sizes, int n_in,
                              void* d_out, int out_size)
{
    const float* x     = (const float*)d_in[0];
    const float* W_enc = (const float*)d_in[1];
    const float* b_enc = (const float*)d_in[2];
    const float* W_dec = (const float*)d_in[3];
    const float* b_dec = (const float*)d_in[4];

    float* xhat = (float*)d_out;
    float* z    = xhat + (size_t)B_SZ * TD;

    static int attr_set = 0;
    if (!attr_set) {
        cudaFuncSetAttribute(encode_mma_kernel,
                             cudaFuncAttributeMaxDynamicSharedMemorySize, SMEM_DYN);
        attr_set = 1;
    }

    split_x_kernel<<<(B_SZ * K_DIM) / 256, 256>>>(x);
    split_w_kernel<<<dim3(D_SAE / 32, K_DIM / 32), 256>>>(W_enc);
    encode_mma_kernel<<<dim3(B_SZ / 128, D_SAE / 256), 256, SMEM_DYN>>>(b_enc, z);
    topk4_kernel<<<B_SZ, 256>>>(z, x, W_enc, b_enc);
    decode_kernel<<<B_SZ, 256>>>(W_dec, b_dec, xhat);
}

// round 16
// speedup vs baseline: 1.0947x; 1.0071x over previous
#include <cuda_runtime.h>
#include <cuda_bf16.h>
#include <cstdint>

// Problem constants
#define B_SZ   1024
#define T_SZ   4
#define D_IN   768
#define D_SAE  16384
#define K_TOP  64
#define K_DIM  3072
#define TD     3072

// ---------------------------------------------------------------------------
// Device scratch (no allocation allowed)
// ---------------------------------------------------------------------------
__device__ __nv_bfloat16 g_xhi[B_SZ * K_DIM];
__device__ __nv_bfloat16 g_xlo[B_SZ * K_DIM];
__device__ __nv_bfloat16 g_whi[(size_t)D_SAE * K_DIM];   // W^T hi, (N, K) row-major
__device__ __nv_bfloat16 g_wlo[(size_t)D_SAE * K_DIM];   // W^T lo
__device__ int   g_idx[B_SZ * K_TOP];
__device__ float g_val[B_SZ * K_TOP];

// ---------------------------------------------------------------------------
// PTX helpers (base sm_80+ features only: cp.async, ldmatrix, mma.sync)
// ---------------------------------------------------------------------------
static __device__ __forceinline__ uint32_t smem_u32(const void* p) {
    uint32_t a;
    asm("{ .reg .u64 t; cvta.to.shared.u64 t, %1; cvt.u32.u64 %0, t; }" : "=r"(a) : "l"(p));
    return a;
}
static __device__ __forceinline__ void cp16(uint32_t dst, const void* src) {
    asm volatile("cp.async.cg.shared.global [%0], [%1], 16;" :: "r"(dst), "l"(src));
}
#define CP_COMMIT() asm volatile("cp.async.commit_group;" ::: "memory")
#define CP_WAIT0()  asm volatile("cp.async.wait_group 0;" ::: "memory")

static __device__ __forceinline__ void ldm4(uint32_t* r, uint32_t addr) {
    asm volatile("ldmatrix.sync.aligned.m8n8.x4.shared.b16 {%0,%1,%2,%3}, [%4];"
                 : "=r"(r[0]), "=r"(r[1]), "=r"(r[2]), "=r"(r[3]) : "r"(addr));
}
static __device__ __forceinline__ void mma16816(float* c, const uint32_t* a, const uint32_t* b) {
    asm volatile(
        "mma.sync.aligned.m16n8k16.row.col.f32.bf16.bf16.f32 "
        "{%0,%1,%2,%3}, {%4,%5,%6,%7}, {%8,%9}, {%0,%1,%2,%3};"
        : "+f"(c[0]), "+f"(c[1]), "+f"(c[2]), "+f"(c[3])
        : "r"(a[0]), "r"(a[1]), "r"(a[2]), "r"(a[3]), "r"(b[0]), "r"(b[1]));
}

// ---------------------------------------------------------------------------
// Split kernels (fp32 -> bf16 hi/lo); W also transposed to (N, K) K-major
// ---------------------------------------------------------------------------
__global__ __launch_bounds__(256) void split_x_kernel(const float* __restrict__ x) {
    int i = blockIdx.x * 256 + threadIdx.x;
    float v = x[i];
    __nv_bfloat16 h = __float2bfloat16(v);
    g_xhi[i] = h;
    g_xlo[i] = __float2bfloat16(v - __bfloat162float(h));
}

// Phase 2 writes 4 consecutive k per thread as one 8B store (conflict-free).
__global__ __launch_bounds__(256) void split_w_kernel(const float* __restrict__ W) {
    __shared__ float t[32][33];           // t[k_local][n_local]
    const int n0 = blockIdx.x * 32, k0 = blockIdx.y * 32;
    const int tx = threadIdx.x & 31, ty = threadIdx.x >> 5;
    #pragma unroll
    for (int j = 0; j < 4; j++)
        t[ty + j * 8][tx] = W[(size_t)(k0 + ty + j * 8) * D_SAE + n0 + tx];
    __syncthreads();

    const int nl = threadIdx.x >> 3;            // 0..31  (n within tile)
    const int kg = (threadIdx.x & 7) * 4;       // 0,4,..28 (k group of 4)
    __nv_bfloat16 hi[4], lo[4];
    #pragma unroll
    for (int e = 0; e < 4; e++) {
        const float v = t[kg + e][nl];
        const __nv_bfloat16 h = __float2bfloat16(v);
        hi[e] = h;
        lo[e] = __float2bfloat16(v - __bfloat162float(h));
    }
    const size_t o = ((size_t)(n0 + nl) * K_DIM + k0 + kg);
    *reinterpret_cast<uint2*>(g_whi + o) = *reinterpret_cast<const uint2*>(hi);
    *reinterpret_cast<uint2*>(g_wlo + o) = *reinterpret_cast<const uint2*>(lo);
}

// ---------------------------------------------------------------------------
// Encode GEMM via mma.sync (HMMA): C = relu(X @ W + b), 3-product bf16 split.
// 128x128 CTA tile, BK=32, TWO-stage double buffer (80KB smem) so TWO CTAs
// co-reside per SM: one CTA's ldmatrix/smem phase overlaps the other's HMMA
// phase (measured: the two floors serialize within one CTA). Prefetch is
// issued right after the barrier so the load overlaps this iter's compute.
// bm-fastest grid: A L2-resident, B streamed from DRAM once.
// ---------------------------------------------------------------------------
#define LDB     80                       // bytes per 32-element bf16 row (64 + 16 pad)
#define MAT_B   (128 * LDB)              // 10240 bytes per matrix tile
#define A_HI    0
#define A_LO    (MAT_B)
#define B_HI    (2 * MAT_B)
#define B_LO    (3 * MAT_B)
#define STAGE_B (4 * MAT_B)              // 40960
#define STAGES  2
#define NITER   (K_DIM / 32)             // 96
#define SMEM_DYN (STAGES * STAGE_B)      // 81920

static __device__ __forceinline__ void load_stage(
    uint32_t st, const __nv_bfloat16* Ah, const __nv_bfloat16* Al,
    const __nv_bfloat16* Bh, const __nv_bfloat16* Bl, int tid, int k0)
{
    #pragma unroll
    for (int i = 0; i < 2; i++) {
        const int j   = tid + i * 256;       // 0..511
        const int row = j >> 2, seg = j & 3;
        const uint32_t so = row * LDB + seg * 16;
        const size_t   go = (size_t)row * K_DIM + k0 + seg * 8;
        cp16(st + A_HI + so, Ah + go);
        cp16(st + A_LO + so, Al + go);
        cp16(st + B_HI + so, Bh + go);
        cp16(st + B_LO + so, Bl + go);
    }
    CP_COMMIT();
}

__global__ __launch_bounds__(256, 2) void encode_mma_kernel(
    const float* __restrict__ bias, float* __restrict__ C)
{
    extern __shared__ __align__(128) char smem[];
    const uint32_t sb = smem_u32(smem);
    const int tid = threadIdx.x, wid = tid >> 5, lane = tid & 31;
    const int wm = wid >> 2, wn = wid & 3;         // warp grid 2(M) x 4(N)
    const int bm = blockIdx.x, bn = blockIdx.y;    // bm fastest for L2 reuse

    const __nv_bfloat16* Ah = g_xhi + (size_t)bm * 128 * K_DIM;
    const __nv_bfloat16* Al = g_xlo + (size_t)bm * 128 * K_DIM;
    const __nv_bfloat16* Bh = g_whi + (size_t)bn * 128 * K_DIM;
    const __nv_bfloat16* Bl = g_wlo + (size_t)bn * 128 * K_DIM;

    // ldmatrix lane address components
    const uint32_t a_off = (uint32_t)((lane & 15) * LDB + (lane >> 4) * 16);
    const uint32_t b_row = (uint32_t)((lane & 7) + (lane >> 4) * 8);
    const uint32_t b_kh  = (uint32_t)(((lane >> 3) & 1) * 16);

    float acc[4][4][4] = {};

    // Prologue: load tile 0 into stage 0
    load_stage(sb, Ah, Al, Bh, Bl, tid, 0);

    for (int it = 0; it < NITER; ++it) {
        CP_WAIT0();             // tile `it` resident
        __syncthreads();        // all threads' iter it-1 reads complete
        const uint32_t st = sb + (it & 1) * STAGE_B;

        // Prefetch tile it+1 into the other stage (read in it-1, drained)
        if (it + 1 < NITER)
            load_stage(sb + ((it + 1) & 1) * STAGE_B, Ah, Al, Bh, Bl, tid, (it + 1) * 32);
        else
            CP_COMMIT();        // empty group keeps wait arithmetic uniform

        #pragma unroll
        for (int ks = 0; ks < 2; ks++) {
            const uint32_t kb = ks * 32;
            uint32_t ah[4][4], al[4][4], bh[4][2], bl[4][2];
            #pragma unroll
            for (int mt = 0; mt < 4; mt++) {
                const uint32_t r = (wm * 64 + mt * 16) * LDB + a_off + kb;
                ldm4(ah[mt], st + A_HI + r);
                ldm4(al[mt], st + A_LO + r);
            }
            #pragma unroll
            for (int p = 0; p < 2; p++) {
                const uint32_t r = (wn * 32 + p * 16 + b_row) * LDB + b_kh + kb;
                uint32_t t[4];
                ldm4(t, st + B_HI + r);
                bh[2*p][0] = t[0]; bh[2*p][1] = t[1];
                bh[2*p+1][0] = t[2]; bh[2*p+1][1] = t[3];
                ldm4(t, st + B_LO + r);
                bl[2*p][0] = t[0]; bl[2*p][1] = t[1];
                bl[2*p+1][0] = t[2]; bl[2*p+1][1] = t[3];
            }
            // Term-major: 16 independent accs between any accumulator reuse
            #pragma unroll
            for (int mt = 0; mt < 4; mt++)
                #pragma unroll
                for (int nt = 0; nt < 4; nt++)
                    mma16816(acc[mt][nt], ah[mt], bh[nt]);
            #pragma unroll
            for (int mt = 0; mt < 4; mt++)
                #pragma unroll
                for (int nt = 0; nt < 4; nt++)
                    mma16816(acc[mt][nt], ah[mt], bl[nt]);
            #pragma unroll
            for (int mt = 0; mt < 4; mt++)
                #pragma unroll
                for (int nt = 0; nt < 4; nt++)
                    mma16816(acc[mt][nt], al[mt], bh[nt]);
        }
    }

    // Epilogue: bias + relu, float2 stores
    #pragma unroll
    for (int nt = 0; nt < 4; nt++) {
        const int col = bn * 128 + wn * 32 + nt * 8 + (lane & 3) * 2;
        const float b0 = bias[col], b1 = bias[col + 1];
        #pragma unroll
        for (int mt = 0; mt < 4; mt++) {
            const int row = bm * 128 + wm * 64 + mt * 16 + (lane >> 2);
            float2 v0, v1;
            v0.x = fmaxf(acc[mt][nt][0] + b0, 0.0f);
            v0.y = fmaxf(acc[mt][nt][1] + b1, 0.0f);
            v1.x = fmaxf(acc[mt][nt][2] + b0, 0.0f);
            v1.y = fmaxf(acc[mt][nt][3] + b1, 0.0f);
            *reinterpret_cast<float2*>(C + (size_t)row * D_SAE + col) = v0;
            *reinterpret_cast<float2*>(C + (size_t)(row + 8) * D_SAE + col) = v1;
        }
    }
}

// ---------------------------------------------------------------------------
// Top-64 (topk4, R9-proven, 143us): 2-pass radix (16-bit bin) + in-smem exact
// select + NARROW refine.
// ---------------------------------------------------------------------------
#define NC_MAX 256
__global__ __launch_bounds__(256) void topk4_kernel(
    float* __restrict__ z, const float* __restrict__ x,
    const float* __restrict__ W, const float* __restrict__ be)
{
    const int b = blockIdx.x, tid = threadIdx.x;
    float* row = z + (size_t)b * D_SAE;
    float4* row4 = reinterpret_cast<float4*>(row);

    __shared__ float xrow[K_DIM];
    __shared__ unsigned int hist[256];
    __shared__ unsigned int sh_prefix;
    __shared__ int sh_kRemain;
    __shared__ int sA, sNC, sNW;
    __shared__ float sT;
    __shared__ int   cidx[NC_MAX];
    __shared__ float cval[NC_MAX];
    __shared__ int   wlist[64];
    __shared__ float red[256];

    for (int i = tid; i < K_DIM; i += 256)
        xrow[i] = x[(size_t)b * K_DIM + i];

    if (tid == 0) { sh_prefix = 0u; sh_kRemain = K_TOP; sA = 0; sNC = 0; sNW = 0; sT = 0.0f; }
    __syncthreads();

    // 2-pass radix select on top 16 bits (values >= 0 post-relu)
    #pragma unroll
    for (int shift = 24; shift >= 16; shift -= 8) {
        hist[tid] = 0u;
        __syncthreads();
        const unsigned int prefix = sh_prefix;
        const unsigned int hmask = (shift == 24) ? 0u : 0xFF000000u;
        for (int i = tid; i < D_SAE / 4; i += 256) {
            float4 v = row4[i];
            #pragma unroll
            for (int e = 0; e < 4; e++) {
                unsigned int bits = __float_as_uint((&v.x)[e]);
                if ((bits & hmask) == prefix)
                    atomicAdd(&hist[(bits >> shift) & 0xFF], 1u);
            }
        }
        __syncthreads();
        if (tid == 0) {
            int cum = 0;
            const int kr = sh_kRemain;
            for (int bin = 255; bin >= 0; bin--) {
                cum += (int)hist[bin];
                if (cum >= kr) {
                    sh_kRemain = kr - (cum - (int)hist[bin]);
                    sh_prefix = prefix | ((unsigned int)bin << shift);
                    break;
                }
            }
        }
        __syncthreads();
    }

    // 16-bit bin [t_lo, t_hi) of the 64th value
    const unsigned int p16 = sh_prefix;
    const float t_lo = __uint_as_float(p16);
    const float t_hi = __uint_as_float(p16 + 0x10000u);
    const float dlt  = 1e-3f * fmaxf(t_lo, 1.0f);       // >> split error ~3e-5
    const float hi_cut = t_hi + dlt;
    const float lo_cut = t_lo - dlt;

    // Classify sweep (float4): winners kept in row; candidates+losers zeroed
    for (int i = tid; i < D_SAE / 4; i += 256) {
        float4 v = row4[i];
        float4 o = v;
        #pragma unroll
        for (int e = 0; e < 4; e++) {
            const float f = (&v.x)[e];
            if (f >= hi_cut) {
                int s = atomicAdd(&sA, 1);
                g_idx[b * K_TOP + s] = i * 4 + e;
                g_val[b * K_TOP + s] = f;
            } else {
                if (f >= lo_cut && f > 0.0f) {
                    int c = atomicAdd(&sNC, 1);
                    if (c < NC_MAX) { cidx[c] = i * 4 + e; cval[c] = f; }
                }
                (&o.x)[e] = 0.0f;
            }
        }
        row4[i] = o;
    }
    __syncthreads();

    const int A = sA;
    const int nc = (sNC < NC_MAX) ? sNC : NC_MAX;
    const int need = K_TOP - A;          // >= 1 by construction

    // Find t = need-th largest candidate (approx, idx tie-break). nc ~ 10.
    for (int c = tid; c < nc; c += 256) {
        const float vc = cval[c];
        const int id = cidx[c];
        int r = 0;
        for (int j = 0; j < nc; j++) {
            const float vj = cval[j];
            r += (vj > vc) || (vj == vc && cidx[j] < id);
        }
        if (r == need - 1) sT = vc;
    }
    __syncthreads();
    const float t = sT;

    // Candidates clearly above t: certain winners (approx values). Window: refine.
    for (int c = tid; c < nc; c += 256) {
        const float vc = cval[c];
        if (vc > t + dlt) {
            int s = atomicAdd(&sA, 1);
            const int m = cidx[c];
            g_idx[b * K_TOP + s] = m;
            g_val[b * K_TOP + s] = vc;
            row[m] = vc;                 // restore (was zeroed in classify)
        } else if (fabsf(vc - t) <= dlt) {
            int w = atomicAdd(&sNW, 1);
            if (w < 64) wlist[w] = c;
        }
    }
    __syncthreads();

    const int nwin = (sNW < 64) ? sNW : 64;
    const int need2 = K_TOP - sA;        // remaining slots for window members

    if (nwin > 0) {
        // Exact fp32 recompute of window members (rare: ~0.3/row)
        for (int k = 0; k < nwin; k++) {
            const int c = wlist[k];
            const int m = cidx[c];
            float p = 0.0f;
            for (int kk = tid; kk < K_DIM; kk += 256)
                p = fmaf(xrow[kk], W[(size_t)kk * D_SAE + m], p);
            red[tid] = p;
            __syncthreads();
            for (int s = 128; s > 0; s >>= 1) {
                if (tid < s) red[tid] += red[tid + s];
                __syncthreads();
            }
            if (tid == 0) cval[c] = fmaxf(red[0] + be[m], 0.0f);
            __syncthreads();
        }

        // Rank window members by exact value (desc, idx asc); keep top need2
        if (tid < nwin) {
            const int c = wlist[tid];
            const int m = cidx[c];
            const float vc = cval[c];
            int r = 0;
            for (int j = 0; j < nwin; j++) {
                if (j == tid) continue;
                const int cj = wlist[j];
                const float vj = cval[cj];
                if (vj > vc || (vj == vc && cidx[cj] < m)) r++;
            }
            if (r < need2) {
                row[m] = vc;
                int s = atomicAdd(&sA, 1);
                g_idx[b * K_TOP + s] = m;
                g_val[b * K_TOP + s] = vc;
            }
        }
    }
}

// ---------------------------------------------------------------------------
// Sparse decode (float4): x_hat[b,t,d] = b_dec[t,d] + sum_s val*W_dec[t,m,d]
// ---------------------------------------------------------------------------
__global__ __launch_bounds__(256) void decode_kernel(
    const float* __restrict__ W_dec, const float* __restrict__ b_dec,
    float* __restrict__ xhat)
{
    const int b = blockIdx.x;
    const int tid = threadIdx.x;
    const float4* W4 = reinterpret_cast<const float4*>(W_dec);
    const float4* bd4 = reinterpret_cast<const float4*>(b_dec);

    __shared__ float sv[K_TOP];
    __shared__ int   si[K_TOP];
    if (tid < K_TOP) {
        sv[tid] = g_val[b * K_TOP + tid];
        si[tid] = g_idx[b * K_TOP + tid];
    }

    float4 acc[3];
    size_t off4[3];
    #pragma unroll
    for (int s = 0; s < 3; s++) {
        const int chunk = tid + s * 256;          // 0..767 float4 chunks
        const int t = chunk / 192;
        const int d4 = chunk - t * 192;
        off4[s] = (size_t)t * D_SAE * 192 + d4;
        acc[s] = bd4[chunk];
    }
    __syncthreads();

    #pragma unroll 2
    for (int i = 0; i < K_TOP; i++) {
        const float v = sv[i];
        const size_t mo = (size_t)si[i] * 192;
        #pragma unroll
        for (int s = 0; s < 3; s++) {
            const float4 w = __ldg(W4 + off4[s] + mo);
            acc[s].x = fmaf(v, w.x, acc[s].x);
            acc[s].y = fmaf(v, w.y, acc[s].y);
            acc[s].z = fmaf(v, w.z, acc[s].z);
            acc[s].w = fmaf(v, w.w, acc[s].w);
        }
    }

    float4* out4 = reinterpret_cast<float4*>(xhat + (size_t)b * TD);
    #pragma unroll
    for (int s = 0; s < 3; s++)
        out4[tid + s * 256] = acc[s];
}

// ---------------------------------------------------------------------------
// Launch
// ---------------------------------------------------------------------------
extern "C" void kernel_launch(void* const* d_in, const int* in_sizes, int n_in,
                              void* d_out, int out_size)
{
    const float* x     = (const float*)d_in[0];
    const float* W_enc = (const float*)d_in[1];
    const float* b_enc = (const float*)d_in[2];
    const float* W_dec = (const float*)d_in[3];
    const float* b_dec = (const float*)d_in[4];

    float* xhat = (float*)d_out;
    float* z    = xhat + (size_t)B_SZ * TD;

    static int attr_set = 0;
    if (!attr_set) {
        cudaFuncSetAttribute(encode_mma_kernel,
                             cudaFuncAttributeMaxDynamicSharedMemorySize, SMEM_DYN);
        attr_set = 1;
    }

    split_x_kernel<<<(B_SZ * K_DIM) / 256, 256>>>(x);
    split_w_kernel<<<dim3(D_SAE / 32, K_DIM / 32), 256>>>(W_enc);
    encode_mma_kernel<<<dim3(B_SZ / 128, D_SAE / 128), 256, SMEM_DYN>>>(b_enc, z);
    topk4_kernel<<<B_SZ, 256>>>(z, x, W_enc, b_enc);
    decode_kernel<<<B_SZ, 256>>>(W_dec, b_dec, xhat);
}

// round 17
// speedup vs baseline: 1.2284x; 1.1222x over previous
#include <cuda_runtime.h>
#include <cuda_fp16.h>
#include <cuda_bf16.h>
#include <cstdint>

// Problem constants
#define B_SZ   1024
#define T_SZ   4
#define D_IN   768
#define D_SAE  16384
#define K_TOP  64
#define K_DIM  3072
#define TD     3072

// ---------------------------------------------------------------------------
// Device scratch (no allocation allowed)
// ---------------------------------------------------------------------------
__device__ __half g_xhi[B_SZ * K_DIM];
__device__ __half g_xlo[B_SZ * K_DIM];
__device__ __half g_whi[(size_t)D_SAE * K_DIM];   // W^T fp16, (N, K) row-major
__device__ int   g_idx[B_SZ * K_TOP];
__device__ float g_val[B_SZ * K_TOP];

// ---------------------------------------------------------------------------
// PTX helpers (base sm_80+ features only: cp.async, ldmatrix, mma.sync)
// ---------------------------------------------------------------------------
static __device__ __forceinline__ uint32_t smem_u32(const void* p) {
    uint32_t a;
    asm("{ .reg .u64 t; cvta.to.shared.u64 t, %1; cvt.u32.u64 %0, t; }" : "=r"(a) : "l"(p));
    return a;
}
static __device__ __forceinline__ void cp16(uint32_t dst, const void* src) {
    asm volatile("cp.async.cg.shared.global [%0], [%1], 16;" :: "r"(dst), "l"(src));
}
#define CP_COMMIT() asm volatile("cp.async.commit_group;" ::: "memory")
#define CP_WAIT2()  asm volatile("cp.async.wait_group 2;" ::: "memory")

static __device__ __forceinline__ void ldm4(uint32_t* r, uint32_t addr) {
    asm volatile("ldmatrix.sync.aligned.m8n8.x4.shared.b16 {%0,%1,%2,%3}, [%4];"
                 : "=r"(r[0]), "=r"(r[1]), "=r"(r[2]), "=r"(r[3]) : "r"(addr));
}
static __device__ __forceinline__ void mma16816(float* c, const uint32_t* a, const uint32_t* b) {
    asm volatile(
        "mma.sync.aligned.m16n8k16.row.col.f32.f16.f16.f32 "
        "{%0,%1,%2,%3}, {%4,%5,%6,%7}, {%8,%9}, {%0,%1,%2,%3};"
        : "+f"(c[0]), "+f"(c[1]), "+f"(c[2]), "+f"(c[3])
        : "r"(a[0]), "r"(a[1]), "r"(a[2]), "r"(a[3]), "r"(b[0]), "r"(b[1]));
}

// ---------------------------------------------------------------------------
// Split kernels: x -> fp16 hi/lo (exact to 2^-22); W -> single fp16, and
// transposed to (N, K) K-major. A-side is exact; W quantization noise
// (rel ~1.2e-4 on pre, random-sign accumulation) dominates the error budget.
// ---------------------------------------------------------------------------
__global__ __launch_bounds__(256) void split_x_kernel(const float* __restrict__ x) {
    int i = blockIdx.x * 256 + threadIdx.x;
    float v = x[i];
    __half h = __float2half(v);
    g_xhi[i] = h;
    g_xlo[i] = __float2half(v - __half2float(h));
}

// Phase 2 writes 4 consecutive k per thread as one 8B store (conflict-free).
__global__ __launch_bounds__(256) void split_w_kernel(const float* __restrict__ W) {
    __shared__ float t[32][33];           // t[k_local][n_local]
    const int n0 = blockIdx.x * 32, k0 = blockIdx.y * 32;
    const int tx = threadIdx.x & 31, ty = threadIdx.x >> 5;
    #pragma unroll
    for (int j = 0; j < 4; j++)
        t[ty + j * 8][tx] = W[(size_t)(k0 + ty + j * 8) * D_SAE + n0 + tx];
    __syncthreads();

    const int nl = threadIdx.x >> 3;            // 0..31  (n within tile)
    const int kg = (threadIdx.x & 7) * 4;       // 0,4,..28 (k group of 4)
    __half hi[4];
    #pragma unroll
    for (int e = 0; e < 4; e++)
        hi[e] = __float2half(t[kg + e][nl]);
    const size_t o = ((size_t)(n0 + nl) * K_DIM + k0 + kg);
    *reinterpret_cast<uint2*>(g_whi + o) = *reinterpret_cast<const uint2*>(hi);
}

// ---------------------------------------------------------------------------
// Encode GEMM via mma.sync (HMMA fp16): C = relu(X @ W + b), TWO products:
// acc += Ah*Bh; acc += Al*Bh  (A exact fp16 pair, B single fp16).
// 33% fewer MMAs than the bf16 3-term split (measured HMMA-issue-bound).
// 128x128 CTA tile, BK=32, 4-stage cp.async pipeline (3 tiles/stage),
// ONE sync per k-iter. bm-fastest grid: A L2-resident, B streamed once.
// ---------------------------------------------------------------------------
#define LDB     80                       // bytes per 32-element fp16 row (64 + 16 pad)
#define MAT_B   (128 * LDB)              // 10240 bytes per matrix tile
#define A_HI    0
#define A_LO    (MAT_B)
#define B_HI    (2 * MAT_B)
#define STAGE_B (3 * MAT_B)              // 30720
#define STAGES  4
#define NITER   (K_DIM / 32)             // 96
#define SMEM_DYN (STAGES * STAGE_B)      // 122880

static __device__ __forceinline__ void load_stage(
    uint32_t st, const __half* Ah, const __half* Al,
    const __half* Bh, int tid, int k0)
{
    #pragma unroll
    for (int i = 0; i < 2; i++) {
        const int j   = tid + i * 256;       // 0..511
        const int row = j >> 2, seg = j & 3;
        const uint32_t so = row * LDB + seg * 16;
        const size_t   go = (size_t)row * K_DIM + k0 + seg * 8;
        cp16(st + A_HI + so, Ah + go);
        cp16(st + A_LO + so, Al + go);
        cp16(st + B_HI + so, Bh + go);
    }
    CP_COMMIT();
}

__global__ __launch_bounds__(256) void encode_mma_kernel(
    const float* __restrict__ bias, float* __restrict__ C)
{
    extern __shared__ __align__(128) char smem[];
    const uint32_t sb = smem_u32(smem);
    const int tid = threadIdx.x, wid = tid >> 5, lane = tid & 31;
    const int wm = wid >> 2, wn = wid & 3;         // warp grid 2(M) x 4(N)
    const int bm = blockIdx.x, bn = blockIdx.y;    // bm fastest for L2 reuse

    const __half* Ah = g_xhi + (size_t)bm * 128 * K_DIM;
    const __half* Al = g_xlo + (size_t)bm * 128 * K_DIM;
    const __half* Bh = g_whi + (size_t)bn * 128 * K_DIM;

    // ldmatrix lane address components
    const uint32_t a_off = (uint32_t)((lane & 15) * LDB + (lane >> 4) * 16);
    const uint32_t b_row = (uint32_t)((lane & 7) + (lane >> 4) * 8);
    const uint32_t b_kh  = (uint32_t)(((lane >> 3) & 1) * 16);

    float acc[4][4][4] = {};

    // Prologue: fill 3 of 4 stages
    for (int s = 0; s < STAGES - 1; s++)
        load_stage(sb + s * STAGE_B, Ah, Al, Bh, tid, s * 32);

    for (int it = 0; it < NITER; ++it) {
        CP_WAIT2();
        __syncthreads();        // single barrier per iter (4-stage WAR-safe)
        const uint32_t st = sb + (it & 3) * STAGE_B;

        #pragma unroll
        for (int ks = 0; ks < 2; ks++) {
            const uint32_t kb = ks * 32;
            uint32_t ah[4][4], al[4][4], bh[4][2];
            #pragma unroll
            for (int mt = 0; mt < 4; mt++) {
                const uint32_t r = (wm * 64 + mt * 16) * LDB + a_off + kb;
                ldm4(ah[mt], st + A_HI + r);
                ldm4(al[mt], st + A_LO + r);
            }
            #pragma unroll
            for (int p = 0; p < 2; p++) {
                const uint32_t r = (wn * 32 + p * 16 + b_row) * LDB + b_kh + kb;
                uint32_t t[4];
                ldm4(t, st + B_HI + r);
                bh[2*p][0] = t[0]; bh[2*p][1] = t[1];
                bh[2*p+1][0] = t[2]; bh[2*p+1][1] = t[3];
            }
            // Term-major: 16 independent accs between any accumulator reuse
            #pragma unroll
            for (int mt = 0; mt < 4; mt++)
                #pragma unroll
                for (int nt = 0; nt < 4; nt++)
                    mma16816(acc[mt][nt], ah[mt], bh[nt]);
            #pragma unroll
            for (int mt = 0; mt < 4; mt++)
                #pragma unroll
                for (int nt = 0; nt < 4; nt++)
                    mma16816(acc[mt][nt], al[mt], bh[nt]);
        }
        const int nxt = it + STAGES - 1;
        if (nxt < NITER)
            load_stage(sb + (nxt & 3) * STAGE_B, Ah, Al, Bh, tid, nxt * 32);
        else
            CP_COMMIT();   // empty group keeps wait_group arithmetic uniform
    }

    // Epilogue: bias + relu, float2 stores
    #pragma unroll
    for (int nt = 0; nt < 4; nt++) {
        const int col = bn * 128 + wn * 32 + nt * 8 + (lane & 3) * 2;
        const float b0 = bias[col], b1 = bias[col + 1];
        #pragma unroll
        for (int mt = 0; mt < 4; mt++) {
            const int row = bm * 128 + wm * 64 + mt * 16 + (lane >> 2);
            float2 v0, v1;
            v0.x = fmaxf(acc[mt][nt][0] + b0, 0.0f);
            v0.y = fmaxf(acc[mt][nt][1] + b1, 0.0f);
            v1.x = fmaxf(acc[mt][nt][2] + b0, 0.0f);
            v1.y = fmaxf(acc[mt][nt][3] + b1, 0.0f);
            *reinterpret_cast<float2*>(C + (size_t)row * D_SAE + col) = v0;
            *reinterpret_cast<float2*>(C + (size_t)(row + 8) * D_SAE + col) = v1;
        }
    }
}

// ---------------------------------------------------------------------------
// Top-64 (topk4 machinery, R9-proven): 2-pass radix (16-bit bin) + in-smem
// exact select + NARROW refine. dlt widened to 2e-3 (>> fp16-W noise 8e-4 max)
// so approximate ordering outside the refine window is provably exact.
// ---------------------------------------------------------------------------
#define NC_MAX 256
__global__ __launch_bounds__(256) void topk4_kernel(
    float* __restrict__ z, const float* __restrict__ x,
    const float* __restrict__ W, const float* __restrict__ be)
{
    const int b = blockIdx.x, tid = threadIdx.x;
    float* row = z + (size_t)b * D_SAE;
    float4* row4 = reinterpret_cast<float4*>(row);

    __shared__ float xrow[K_DIM];
    __shared__ unsigned int hist[256];
    __shared__ unsigned int sh_prefix;
    __shared__ int sh_kRemain;
    __shared__ int sA, sNC, sNW;
    __shared__ float sT;
    __shared__ int   cidx[NC_MAX];
    __shared__ float cval[NC_MAX];
    __shared__ int   wlist[64];
    __shared__ float red[256];

    for (int i = tid; i < K_DIM; i += 256)
        xrow[i] = x[(size_t)b * K_DIM + i];

    if (tid == 0) { sh_prefix = 0u; sh_kRemain = K_TOP; sA = 0; sNC = 0; sNW = 0; sT = 0.0f; }
    __syncthreads();

    // 2-pass radix select on top 16 bits (values >= 0 post-relu)
    #pragma unroll
    for (int shift = 24; shift >= 16; shift -= 8) {
        hist[tid] = 0u;
        __syncthreads();
        const unsigned int prefix = sh_prefix;
        const unsigned int hmask = (shift == 24) ? 0u : 0xFF000000u;
        for (int i = tid; i < D_SAE / 4; i += 256) {
            float4 v = row4[i];
            #pragma unroll
            for (int e = 0; e < 4; e++) {
                unsigned int bits = __float_as_uint((&v.x)[e]);
                if ((bits & hmask) == prefix)
                    atomicAdd(&hist[(bits >> shift) & 0xFF], 1u);
            }
        }
        __syncthreads();
        if (tid == 0) {
            int cum = 0;
            const int kr = sh_kRemain;
            for (int bin = 255; bin >= 0; bin--) {
                cum += (int)hist[bin];
                if (cum >= kr) {
                    sh_kRemain = kr - (cum - (int)hist[bin]);
                    sh_prefix = prefix | ((unsigned int)bin << shift);
                    break;
                }
            }
        }
        __syncthreads();
    }

    // 16-bit bin [t_lo, t_hi) of the 64th value
    const unsigned int p16 = sh_prefix;
    const float t_lo = __uint_as_float(p16);
    const float t_hi = __uint_as_float(p16 + 0x10000u);
    const float dlt  = 2e-3f * fmaxf(t_lo, 1.0f);       // >> fp16-W noise (~8e-4 max)
    const float hi_cut = t_hi + dlt;
    const float lo_cut = t_lo - dlt;

    // Classify sweep (float4): winners kept in row; candidates+losers zeroed
    for (int i = tid; i < D_SAE / 4; i += 256) {
        float4 v = row4[i];
        float4 o = v;
        #pragma unroll
        for (int e = 0; e < 4; e++) {
            const float f = (&v.x)[e];
            if (f >= hi_cut) {
                int s = atomicAdd(&sA, 1);
                g_idx[b * K_TOP + s] = i * 4 + e;
                g_val[b * K_TOP + s] = f;
            } else {
                if (f >= lo_cut && f > 0.0f) {
                    int c = atomicAdd(&sNC, 1);
                    if (c < NC_MAX) { cidx[c] = i * 4 + e; cval[c] = f; }
                }
                (&o.x)[e] = 0.0f;
            }
        }
        row4[i] = o;
    }
    __syncthreads();

    const int A = sA;
    const int nc = (sNC < NC_MAX) ? sNC : NC_MAX;
    const int need = K_TOP - A;          // >= 1 by construction

    // Find t = need-th largest candidate (approx, idx tie-break). nc ~ 12.
    for (int c = tid; c < nc; c += 256) {
        const float vc = cval[c];
        const int id = cidx[c];
        int r = 0;
        for (int j = 0; j < nc; j++) {
            const float vj = cval[j];
            r += (vj > vc) || (vj == vc && cidx[j] < id);
        }
        if (r == need - 1) sT = vc;
    }
    __syncthreads();
    const float t = sT;

    // Candidates clearly above t: certain winners (approx values). Window: refine.
    for (int c = tid; c < nc; c += 256) {
        const float vc = cval[c];
        if (vc > t + dlt) {
            int s = atomicAdd(&sA, 1);
            const int m = cidx[c];
            g_idx[b * K_TOP + s] = m;
            g_val[b * K_TOP + s] = vc;
            row[m] = vc;                 // restore (was zeroed in classify)
        } else if (fabsf(vc - t) <= dlt) {
            int w = atomicAdd(&sNW, 1);
            if (w < 64) wlist[w] = c;
        }
    }
    __syncthreads();

    const int nwin = (sNW < 64) ? sNW : 64;
    const int need2 = K_TOP - sA;        // remaining slots for window members

    if (nwin > 0) {
        // Exact fp32 recompute of window members (~1-2/row)
        for (int k = 0; k < nwin; k++) {
            const int c = wlist[k];
            const int m = cidx[c];
            float p = 0.0f;
            for (int kk = tid; kk < K_DIM; kk += 256)
                p = fmaf(xrow[kk], W[(size_t)kk * D_SAE + m], p);
            red[tid] = p;
            __syncthreads();
            for (int s = 128; s > 0; s >>= 1) {
                if (tid < s) red[tid] += red[tid + s];
                __syncthreads();
            }
            if (tid == 0) cval[c] = fmaxf(red[0] + be[m], 0.0f);
            __syncthreads();
        }

        // Rank window members by exact value (desc, idx asc); keep top need2
        if (tid < nwin) {
            const int c = wlist[tid];
            const int m = cidx[c];
            const float vc = cval[c];
            int r = 0;
            for (int j = 0; j < nwin; j++) {
                if (j == tid) continue;
                const int cj = wlist[j];
                const float vj = cval[cj];
                if (vj > vc || (vj == vc && cidx[cj] < m)) r++;
            }
            if (r < need2) {
                row[m] = vc;
                int s = atomicAdd(&sA, 1);
                g_idx[b * K_TOP + s] = m;
                g_val[b * K_TOP + s] = vc;
            }
        }
    }
}

// ---------------------------------------------------------------------------
// Sparse decode (float4): x_hat[b,t,d] = b_dec[t,d] + sum_s val*W_dec[t,m,d]
// ---------------------------------------------------------------------------
__global__ __launch_bounds__(256) void decode_kernel(
    const float* __restrict__ W_dec, const float* __restrict__ b_dec,
    float* __restrict__ xhat)
{
    const int b = blockIdx.x;
    const int tid = threadIdx.x;
    const float4* W4 = reinterpret_cast<const float4*>(W_dec);
    const float4* bd4 = reinterpret_cast<const float4*>(b_dec);

    __shared__ float sv[K_TOP];
    __shared__ int   si[K_TOP];
    if (tid < K_TOP) {
        sv[tid] = g_val[b * K_TOP + tid];
        si[tid] = g_idx[b * K_TOP + tid];
    }

    float4 acc[3];
    size_t off4[3];
    #pragma unroll
    for (int s = 0; s < 3; s++) {
        const int chunk = tid + s * 256;          // 0..767 float4 chunks
        const int t = chunk / 192;
        const int d4 = chunk - t * 192;
        off4[s] = (size_t)t * D_SAE * 192 + d4;
        acc[s] = bd4[chunk];
    }
    __syncthreads();

    #pragma unroll 2
    for (int i = 0; i < K_TOP; i++) {
        const float v = sv[i];
        const size_t mo = (size_t)si[i] * 192;
        #pragma unroll
        for (int s = 0; s < 3; s++) {
            const float4 w = __ldg(W4 + off4[s] + mo);
            acc[s].x = fmaf(v, w.x, acc[s].x);
            acc[s].y = fmaf(v, w.y, acc[s].y);
            acc[s].z = fmaf(v, w.z, acc[s].z);
            acc[s].w = fmaf(v, w.w, acc[s].w);
        }
    }

    float4* out4 = reinterpret_cast<float4*>(xhat + (size_t)b * TD);
    #pragma unroll
    for (int s = 0; s < 3; s++)
        out4[tid + s * 256] = acc[s];
}

// ---------------------------------------------------------------------------
// Launch
// ---------------------------------------------------------------------------
extern "C" void kernel_launch(void* const* d_in, const int* in_sizes, int n_in,
                              void* d_out, int out_size)
{
    const float* x     = (const float*)d_in[0];
    const float* W_enc = (const float*)d_in[1];
    const float* b_enc = (const float*)d_in[2];
    const float* W_dec = (const float*)d_in[3];
    const float* b_dec = (const float*)d_in[4];

    float* xhat = (float*)d_out;
    float* z    = xhat + (size_t)B_SZ * TD;

    static int attr_set = 0;
    if (!attr_set) {
        cudaFuncSetAttribute(encode_mma_kernel,
                             cudaFuncAttributeMaxDynamicSharedMemorySize, SMEM_DYN);
        attr_set = 1;
    }

    split_x_kernel<<<(B_SZ * K_DIM) / 256, 256>>>(x);
    split_w_kernel<<<dim3(D_SAE / 32, K_DIM / 32), 256>>>(W_enc);
    encode_mma_kernel<<<dim3(B_SZ / 128, D_SAE / 128), 256, SMEM_DYN>>>(b_enc, z);
    topk4_kernel<<<B_SZ, 256>>>(z, x, W_enc, b_enc);
    decode_kernel<<<B_SZ, 256>>>(W_dec, b_dec, xhat);
}